// round 2
// baseline (speedup 1.0000x reference)
#include <cuda_runtime.h>
#include <cstdint>

#define N_NODES 50000
#define N_EDGES 800000
#define DMAX 512

// ---------------- scratch (static device globals; no runtime allocation) ----
__device__ float g_agg[N_NODES * DMAX];
__device__ float g_h1[N_NODES * DMAX];
__device__ float g_h2[N_NODES * DMAX];
__device__ int   g_deg[N_NODES];
__device__ int   g_off[N_NODES + 1];
__device__ int   g_cur[N_NODES];
__device__ int   g_srcs[N_EDGES];
__device__ int   g_idx64;

// ---------------- dtype detection -------------------------------------------
// int64 indices < 50000 have zero high words at every odd int32 position.
// int32 edge data has real (mostly nonzero) indices there.
__global__ void detect_kernel(const int* __restrict__ ei32) {
    int is64 = 1;
    for (int i = 1; i < 2048; i += 2) {
        if (ei32[i] != 0) { is64 = 0; break; }
    }
    g_idx64 = is64;
}

__device__ __forceinline__ int load_idx(const void* ei, long long pos) {
    if (g_idx64) return (int)((const long long*)ei)[pos];
    return ((const int*)ei)[pos];
}

// ---------------- CSR build --------------------------------------------------
__global__ void zero_counts_kernel() {
    int i = blockIdx.x * blockDim.x + threadIdx.x;
    if (i < N_NODES) { g_deg[i] = 0; g_cur[i] = 0; }
}

__global__ void hist_kernel(const void* __restrict__ ei) {
    int e = blockIdx.x * blockDim.x + threadIdx.x;
    if (e < N_EDGES) {
        int d = load_idx(ei, (long long)N_EDGES + e);
        if ((unsigned)d < (unsigned)N_NODES) atomicAdd(&g_deg[d], 1);
    }
}

// Single-block chunked Hillis-Steele scan over 50000 counts -> exclusive offsets.
__global__ void scan_kernel() {
    __shared__ int sh[1024];
    __shared__ int carry;
    int tid = threadIdx.x;
    if (tid == 0) carry = 0;
    __syncthreads();
    for (int base = 0; base < N_NODES; base += 1024) {
        int i = base + tid;
        int v = (i < N_NODES) ? g_deg[i] : 0;
        sh[tid] = v;
        __syncthreads();
        for (int ofs = 1; ofs < 1024; ofs <<= 1) {
            int t = (tid >= ofs) ? sh[tid - ofs] : 0;
            __syncthreads();
            sh[tid] += t;
            __syncthreads();
        }
        int c = carry;
        if (i < N_NODES) g_off[i + 1] = c + sh[tid];
        int tot = sh[1023];
        __syncthreads();
        if (tid == 0) carry = c + tot;
        __syncthreads();
    }
    if (tid == 0) g_off[0] = 0;
}

__global__ void scatter_kernel(const void* __restrict__ ei) {
    int e = blockIdx.x * blockDim.x + threadIdx.x;
    if (e < N_EDGES) {
        int s = load_idx(ei, e);
        int d = load_idx(ei, (long long)N_EDGES + e);
        if ((unsigned)d < (unsigned)N_NODES && (unsigned)s < (unsigned)N_NODES) {
            int pos = atomicAdd(&g_cur[d], 1);
            g_srcs[g_off[d] + pos] = s;
        }
    }
}

// ---------------- mean aggregation: one warp per node ------------------------
template <int D>
__global__ void aggregate_kernel(const float* __restrict__ feat,
                                 float* __restrict__ out) {
    int warp = (blockIdx.x * blockDim.x + threadIdx.x) >> 5;
    if (warp >= N_NODES) return;
    int lane = threadIdx.x & 31;
    int beg = g_off[warp];
    int end = g_off[warp + 1];

    float acc[D / 32];
#pragma unroll
    for (int j = 0; j < D / 32; j++) acc[j] = 0.0f;

    for (int i = beg; i < end; i++) {
        const float* row = feat + (size_t)g_srcs[i] * D;
#pragma unroll
        for (int j = 0; j < D / 32; j++) acc[j] += row[lane + 32 * j];
    }

    int cnt = end - beg;
    float inv = 1.0f / (float)(cnt > 0 ? cnt : 1);
    float* o = out + (size_t)warp * D;
#pragma unroll
    for (int j = 0; j < D / 32; j++) o[lane + 32 * j] = acc[j] * inv;
}

// ---------------- fused dual-A SGEMM: C = A1@W1^T + A2@W2^T + bias (opt relu)
// W is [N, K] row-major (PyTorch Linear layout). BM=BN=128, BK=8, 256 threads,
// 8x8 micro-tile per thread.
template <bool RELU>
__global__ void __launch_bounds__(256)
gemm_dual_kernel(const float* __restrict__ A1, const float* __restrict__ W1,
                 const float* __restrict__ A2, const float* __restrict__ W2,
                 const float* __restrict__ bias, float* __restrict__ C,
                 int M, int N, int K) {
    __shared__ float As[8][128];
    __shared__ float Bs[8][128];

    int tid  = threadIdx.x;
    int bm   = blockIdx.x * 128;
    int bn   = blockIdx.y * 128;
    int lrow = tid >> 1;          // 0..127
    int lk4  = (tid & 1) * 4;     // 0 or 4
    int trow = (tid >> 4) * 8;    // 0..120
    int tcol = (tid & 15) * 8;    // 0..120

    float acc[8][8];
#pragma unroll
    for (int i = 0; i < 8; i++)
#pragma unroll
        for (int j = 0; j < 8; j++) acc[i][j] = 0.0f;

#pragma unroll 1
    for (int pass = 0; pass < 2; pass++) {
        const float* A = pass ? A2 : A1;
        const float* W = pass ? W2 : W1;
        for (int k0 = 0; k0 < K; k0 += 8) {
            float4 av = make_float4(0.f, 0.f, 0.f, 0.f);
            if (bm + lrow < M)
                av = *(const float4*)&A[(size_t)(bm + lrow) * K + k0 + lk4];
            As[lk4 + 0][lrow] = av.x;
            As[lk4 + 1][lrow] = av.y;
            As[lk4 + 2][lrow] = av.z;
            As[lk4 + 3][lrow] = av.w;

            float4 bv = *(const float4*)&W[(size_t)(bn + lrow) * K + k0 + lk4];
            Bs[lk4 + 0][lrow] = bv.x;
            Bs[lk4 + 1][lrow] = bv.y;
            Bs[lk4 + 2][lrow] = bv.z;
            Bs[lk4 + 3][lrow] = bv.w;
            __syncthreads();

#pragma unroll
            for (int kk = 0; kk < 8; kk++) {
                float ra[8], rb[8];
#pragma unroll
                for (int i = 0; i < 8; i++) ra[i] = As[kk][trow + i];
#pragma unroll
                for (int j = 0; j < 8; j++) rb[j] = Bs[kk][tcol + j];
#pragma unroll
                for (int i = 0; i < 8; i++)
#pragma unroll
                    for (int j = 0; j < 8; j++) acc[i][j] += ra[i] * rb[j];
            }
            __syncthreads();
        }
    }

#pragma unroll
    for (int i = 0; i < 8; i++) {
        int m = bm + trow + i;
        if (m >= M) continue;
#pragma unroll
        for (int j = 0; j < 8; j++) {
            int n = bn + tcol + j;
            float v = acc[i][j] + bias[n];
            if (RELU) v = v > 0.0f ? v : 0.0f;
            C[(size_t)m * N + n] = v;
        }
    }
}

// ---------------- launch ------------------------------------------------------
extern "C" void kernel_launch(void* const* d_in, const int* in_sizes, int n_in,
                              void* d_out, int out_size) {
    const float* x   = (const float*)d_in[0];
    const void*  ei  = d_in[1];
    const float* Wl0 = (const float*)d_in[2];
    const float* bl0 = (const float*)d_in[3];
    const float* Wr0 = (const float*)d_in[4];
    const float* Wl1 = (const float*)d_in[5];
    const float* bl1 = (const float*)d_in[6];
    const float* Wr1 = (const float*)d_in[7];
    const float* Wl2 = (const float*)d_in[8];
    const float* bl2 = (const float*)d_in[9];
    const float* Wr2 = (const float*)d_in[10];
    float*       out = (float*)d_out;

    int M = in_sizes[0] / 128;   // 50000

    float *agg, *h1, *h2;
    cudaGetSymbolAddress((void**)&agg, g_agg);
    cudaGetSymbolAddress((void**)&h1,  g_h1);
    cudaGetSymbolAddress((void**)&h2,  g_h2);

    // CSR build (dst-sorted adjacency), rebuilt every call (no caching).
    detect_kernel<<<1, 1>>>((const int*)ei);
    zero_counts_kernel<<<(N_NODES + 255) / 256, 256>>>();
    hist_kernel<<<(N_EDGES + 255) / 256, 256>>>(ei);
    scan_kernel<<<1, 1024>>>();
    scatter_kernel<<<(N_EDGES + 255) / 256, 256>>>(ei);

    int aggBlocks = (N_NODES * 32 + 255) / 256;

    // Layer 0: 128 -> 512, relu
    aggregate_kernel<128><<<aggBlocks, 256>>>(x, agg);
    {
        dim3 grid((M + 127) / 128, 512 / 128);
        gemm_dual_kernel<true><<<grid, 256>>>(agg, Wl0, x, Wr0, bl0, h1, M, 512, 128);
    }

    // Layer 1: 512 -> 512, relu
    aggregate_kernel<512><<<aggBlocks, 256>>>(h1, agg);
    {
        dim3 grid((M + 127) / 128, 512 / 128);
        gemm_dual_kernel<true><<<grid, 256>>>(agg, Wl1, h1, Wr1, bl1, h2, M, 512, 512);
    }

    // Layer 2: 512 -> 256, no activation
    aggregate_kernel<512><<<aggBlocks, 256>>>(h2, agg);
    {
        dim3 grid((M + 127) / 128, 256 / 128);
        gemm_dual_kernel<false><<<grid, 256>>>(agg, Wl2, h2, Wr2, bl2, out, M, 256, 512);
    }
}

// round 4
// speedup vs baseline: 2.3878x; 2.3878x over previous
#include <cuda_runtime.h>
#include <cstdint>

#define N_NODES 50000
#define N_EDGES 800000
#define DMAX 512

// ===================== scratch =================================================
__device__ float g_agg[N_NODES * DMAX];
__device__ float g_h1[N_NODES * DMAX];
__device__ float g_h2[N_NODES * DMAX];
__device__ int   g_deg[N_NODES];
__device__ int   g_off[N_NODES + 1];
__device__ int   g_cur[N_NODES];
__device__ int   g_srcs[N_EDGES];
__device__ int   g_idx64;

__device__ __forceinline__ uint32_t f2tf32(float f) {
    uint32_t r;
    asm("cvt.rna.tf32.f32 %0, %1;" : "=r"(r) : "f"(f));
    return r;
}

__device__ __forceinline__ void mma_tf32(float* c, const uint32_t* a, const uint32_t* b) {
    asm volatile(
        "mma.sync.aligned.m16n8k8.row.col.f32.tf32.tf32.f32 "
        "{%0,%1,%2,%3}, {%4,%5,%6,%7}, {%8,%9}, {%0,%1,%2,%3};"
        : "+f"(c[0]), "+f"(c[1]), "+f"(c[2]), "+f"(c[3])
        : "r"(a[0]), "r"(a[1]), "r"(a[2]), "r"(a[3]), "r"(b[0]), "r"(b[1]));
}

// ===================== dtype detect (1 warp) ==================================
__global__ void detect_kernel(const int* __restrict__ ei32) {
    int lane = threadIdx.x;
    int nz = 0;
#pragma unroll
    for (int t = 0; t < 32; t++) nz |= ei32[1 + 2 * (lane + 32 * t)];
    unsigned any = __ballot_sync(0xffffffffu, nz != 0);
    if (lane == 0) g_idx64 = (any == 0u);
}

__device__ __forceinline__ int load_idx(const void* ei, long long pos) {
    if (g_idx64) return (int)((const long long*)ei)[pos];
    return ((const int*)ei)[pos];
}

// ===================== CSR build ==============================================
__global__ void zero_counts_kernel() {
    int i = blockIdx.x * blockDim.x + threadIdx.x;
    if (i < N_NODES) { g_deg[i] = 0; g_cur[i] = 0; }
}

__global__ void hist_kernel(const void* __restrict__ ei) {
    int e = blockIdx.x * blockDim.x + threadIdx.x;
    if (e < N_EDGES) {
        int d = load_idx(ei, (long long)N_EDGES + e);
        if ((unsigned)d < (unsigned)N_NODES) atomicAdd(&g_deg[d], 1);
    }
}

// 1 block, 1024 threads: 49 elems/thread serial + shuffle block scan.
__global__ void scan_kernel() {
    __shared__ int wsum[32];
    int tid = threadIdx.x;
    int base = tid * 49;
    int v[49];
    int s = 0;
#pragma unroll
    for (int j = 0; j < 49; j++) {
        int i = base + j;
        int d = (i < N_NODES) ? g_deg[i] : 0;
        v[j] = s;
        s += d;
    }
    int lane = tid & 31, w = tid >> 5;
    int ss = s;
#pragma unroll
    for (int o = 1; o < 32; o <<= 1) {
        int t = __shfl_up_sync(0xffffffffu, ss, o);
        if (lane >= o) ss += t;
    }
    if (lane == 31) wsum[w] = ss;
    __syncthreads();
    if (w == 0) {
        int t = wsum[lane];
#pragma unroll
        for (int o = 1; o < 32; o <<= 1) {
            int u = __shfl_up_sync(0xffffffffu, t, o);
            if (lane >= o) t += u;
        }
        wsum[lane] = t;
    }
    __syncthreads();
    int pre = ((w > 0) ? wsum[w - 1] : 0) + (ss - s);
#pragma unroll
    for (int j = 0; j < 49; j++) {
        int i = base + j;
        if (i < N_NODES) g_off[i] = pre + v[j];
    }
    if (tid == 0) g_off[N_NODES] = wsum[31];
}

__global__ void scatter_kernel(const void* __restrict__ ei) {
    int e = blockIdx.x * blockDim.x + threadIdx.x;
    if (e < N_EDGES) {
        int s = load_idx(ei, e);
        int d = load_idx(ei, (long long)N_EDGES + e);
        if ((unsigned)d < (unsigned)N_NODES && (unsigned)s < (unsigned)N_NODES) {
            int pos = atomicAdd(&g_cur[d], 1);
            g_srcs[g_off[d] + pos] = s;
        }
    }
}

// ===================== mean aggregation (warp/node, float4) ==================
template <int D>
__global__ void aggregate_kernel(const float* __restrict__ feat,
                                 float* __restrict__ out) {
    int warp = (blockIdx.x * blockDim.x + threadIdx.x) >> 5;
    if (warp >= N_NODES) return;
    int lane = threadIdx.x & 31;
    int beg = g_off[warp];
    int end = g_off[warp + 1];
    constexpr int C = D / 128;

    float4 acc[C];
#pragma unroll
    for (int j = 0; j < C; j++) acc[j] = make_float4(0.f, 0.f, 0.f, 0.f);

    for (int i = beg; i < end; i++) {
        const float4* row = (const float4*)(feat + (size_t)g_srcs[i] * D);
#pragma unroll
        for (int j = 0; j < C; j++) {
            float4 v = __ldg(&row[lane + 32 * j]);
            acc[j].x += v.x; acc[j].y += v.y; acc[j].z += v.z; acc[j].w += v.w;
        }
    }
    int cnt = end - beg;
    float inv = 1.0f / (float)(cnt > 0 ? cnt : 1);
    float4* o = (float4*)(out + (size_t)warp * D);
#pragma unroll
    for (int j = 0; j < C; j++) {
        float4 r = acc[j];
        r.x *= inv; r.y *= inv; r.z *= inv; r.w *= inv;
        o[lane + 32 * j] = r;
    }
}

// ===================== tf32 mma.sync dual-A GEMM ==============================
// C[M,N] = A1@W1^T + A2@W2^T + bias (+relu). W is [N,K] row-major.
// CTA tile 128x128, BK=32, 8 warps in 2(M)x4(N), warp tile 64x32.
// Smem rows padded to 36 words -> fragment loads conflict-free (4r+c pattern).
template <bool RELU>
__global__ void __launch_bounds__(256, 2)
gemm_mma_kernel(const float* __restrict__ A1, const float* __restrict__ W1,
                const float* __restrict__ A2, const float* __restrict__ W2,
                const float* __restrict__ bias, float* __restrict__ C,
                int M, int N, int K) {
    __shared__ uint32_t As[128][36];
    __shared__ uint32_t Bs[128][36];

    int tid = threadIdx.x, lane = tid & 31, wid = tid >> 5;
    int bm = blockIdx.x * 128, bn = blockIdx.y * 128;
    int wm = wid & 1, wn = wid >> 1;   // warp coords: 2 x 4

    float acc[4][4][4];
#pragma unroll
    for (int mi = 0; mi < 4; mi++)
#pragma unroll
        for (int ni = 0; ni < 4; ni++)
#pragma unroll
            for (int r = 0; r < 4; r++) acc[mi][ni][r] = 0.0f;

    int chunks = K >> 5;
    int total = 2 * chunks;
    int lrow = tid >> 3, lq = tid & 7;   // loader: row 0..31 (+32*t), float4 idx

    for (int it = 0; it < total; it++) {
        int pass = (it >= chunks);
        int k0 = (pass ? it - chunks : it) << 5;
        const float* A = pass ? A2 : A1;
        const float* W = pass ? W2 : W1;

#pragma unroll
        for (int t = 0; t < 4; t++) {
            int row = lrow + t * 32;
            int gr = bm + row;
            float4 v = make_float4(0.f, 0.f, 0.f, 0.f);
            if (gr < M) v = *(const float4*)(A + (size_t)gr * K + k0 + lq * 4);
            uint32_t* p = &As[row][lq * 4];
            p[0] = f2tf32(v.x); p[1] = f2tf32(v.y);
            p[2] = f2tf32(v.z); p[3] = f2tf32(v.w);
        }
#pragma unroll
        for (int t = 0; t < 4; t++) {
            int row = lrow + t * 32;
            float4 v = *(const float4*)(W + (size_t)(bn + row) * K + k0 + lq * 4);
            uint32_t* p = &Bs[row][lq * 4];
            p[0] = f2tf32(v.x); p[1] = f2tf32(v.y);
            p[2] = f2tf32(v.z); p[3] = f2tf32(v.w);
        }
        __syncthreads();

#pragma unroll
        for (int ka = 0; ka < 4; ka++) {
            int kb = ka * 8;
            int qr = lane >> 2, qc = lane & 3;
            uint32_t a[4][4], b[4][2];
#pragma unroll
            for (int mi = 0; mi < 4; mi++) {
                int rb = wm * 64 + mi * 16 + qr;
                a[mi][0] = As[rb][kb + qc];
                a[mi][1] = As[rb + 8][kb + qc];
                a[mi][2] = As[rb][kb + qc + 4];
                a[mi][3] = As[rb + 8][kb + qc + 4];
            }
#pragma unroll
            for (int ni = 0; ni < 4; ni++) {
                int cb = wn * 32 + ni * 8 + qr;
                b[ni][0] = Bs[cb][kb + qc];
                b[ni][1] = Bs[cb][kb + qc + 4];
            }
#pragma unroll
            for (int mi = 0; mi < 4; mi++)
#pragma unroll
                for (int ni = 0; ni < 4; ni++)
                    mma_tf32(acc[mi][ni], a[mi], b[ni]);
        }
        __syncthreads();
    }

    // epilogue: c0,c1 -> (row=qr, col=2*qc..+1); c2,c3 -> row=qr+8
    int qr = lane >> 2, qc2 = (lane & 3) * 2;
#pragma unroll
    for (int mi = 0; mi < 4; mi++) {
#pragma unroll
        for (int half = 0; half < 2; half++) {
            int row = bm + wm * 64 + mi * 16 + qr + half * 8;
            if (row >= M) continue;
#pragma unroll
            for (int ni = 0; ni < 4; ni++) {
                int col = bn + wn * 32 + ni * 8 + qc2;
                float2 o;
                o.x = acc[mi][ni][half * 2 + 0] + bias[col];
                o.y = acc[mi][ni][half * 2 + 1] + bias[col + 1];
                if (RELU) { o.x = fmaxf(o.x, 0.f); o.y = fmaxf(o.y, 0.f); }
                *(float2*)(C + (size_t)row * N + col) = o;
            }
        }
    }
}

// ===================== launch ==================================================
extern "C" void kernel_launch(void* const* d_in, const int* in_sizes, int n_in,
                              void* d_out, int out_size) {
    const float* x   = (const float*)d_in[0];
    const void*  ei  = d_in[1];
    const float* Wl0 = (const float*)d_in[2];
    const float* bl0 = (const float*)d_in[3];
    const float* Wr0 = (const float*)d_in[4];
    const float* Wl1 = (const float*)d_in[5];
    const float* bl1 = (const float*)d_in[6];
    const float* Wr1 = (const float*)d_in[7];
    const float* Wl2 = (const float*)d_in[8];
    const float* bl2 = (const float*)d_in[9];
    const float* Wr2 = (const float*)d_in[10];
    float*       out = (float*)d_out;

    int M = in_sizes[0] / 128;   // 50000

    float *agg, *h1, *h2;
    cudaGetSymbolAddress((void**)&agg, g_agg);
    cudaGetSymbolAddress((void**)&h1,  g_h1);
    cudaGetSymbolAddress((void**)&h2,  g_h2);

    // CSR build (rebuilt every call)
    detect_kernel<<<1, 32>>>((const int*)ei);
    zero_counts_kernel<<<(N_NODES + 255) / 256, 256>>>();
    hist_kernel<<<(N_EDGES + 255) / 256, 256>>>(ei);
    scan_kernel<<<1, 1024>>>();
    scatter_kernel<<<(N_EDGES + 255) / 256, 256>>>(ei);

    int aggBlocks = (N_NODES * 32 + 255) / 256;
    int mTiles = (M + 127) / 128;

    // Layer 0: 128 -> 512, relu
    aggregate_kernel<128><<<aggBlocks, 256>>>(x, agg);
    gemm_mma_kernel<true><<<dim3(mTiles, 4), 256>>>(agg, Wl0, x, Wr0, bl0, h1, M, 512, 128);

    // Layer 1: 512 -> 512, relu
    aggregate_kernel<512><<<aggBlocks, 256>>>(h1, agg);
    gemm_mma_kernel<true><<<dim3(mTiles, 4), 256>>>(agg, Wl1, h1, Wr1, bl1, h2, M, 512, 512);

    // Layer 2: 512 -> 256, no activation
    aggregate_kernel<512><<<aggBlocks, 256>>>(h2, agg);
    gemm_mma_kernel<false><<<dim3(mTiles, 2), 256>>>(agg, Wl2, h2, Wr2, bl2, out, M, 256, 512);
}

// round 5
// speedup vs baseline: 3.6384x; 1.5237x over previous
#include <cuda_runtime.h>
#include <cstdint>

#define N_NODES 50000
#define N_EDGES 800000
#define DMAX 512

// ===================== scratch =================================================
__device__ float g_agg[N_NODES * DMAX];   // agg outputs; layer2: P|R [M,512]
__device__ float g_h1[N_NODES * DMAX];
__device__ float g_h2[N_NODES * DMAX];
__device__ float g_xr[N_NODES * 128];     // tf32-rounded x
__device__ float g_wr[917504];            // tf32-rounded weights
__device__ int   g_deg[N_NODES];
__device__ int   g_off[N_NODES + 1];
__device__ int   g_cur[N_NODES];
__device__ int   g_srcs[N_EDGES];
__device__ int   g_bsum[64];
__device__ int   g_boff[64];
__device__ int   g_idx64;

__device__ __forceinline__ uint32_t f2tf32(float f) {
    uint32_t r;
    asm("cvt.rna.tf32.f32 %0, %1;" : "=r"(r) : "f"(f));
    return r;
}
__device__ __forceinline__ float roundtf(float f) { return __uint_as_float(f2tf32(f)); }

__device__ __forceinline__ void mma_tf32(float* c, const uint32_t* a, const uint32_t* b) {
    asm volatile(
        "mma.sync.aligned.m16n8k8.row.col.f32.tf32.tf32.f32 "
        "{%0,%1,%2,%3}, {%4,%5,%6,%7}, {%8,%9}, {%0,%1,%2,%3};"
        : "+f"(c[0]), "+f"(c[1]), "+f"(c[2]), "+f"(c[3])
        : "r"(a[0]), "r"(a[1]), "r"(a[2]), "r"(a[3]), "r"(b[0]), "r"(b[1]));
}

__device__ __forceinline__ void cp_async16(uint32_t dst, const void* src, int sz) {
    asm volatile("cp.async.cg.shared.global [%0], [%1], 16, %2;"
                 :: "r"(dst), "l"(src), "r"(sz) : "memory");
}
#define CP_COMMIT() asm volatile("cp.async.commit_group;" ::: "memory")
#define CP_WAIT1()  asm volatile("cp.async.wait_group 1;" ::: "memory")

__device__ __forceinline__ uint32_t smem_u32(const void* p) {
    uint32_t a;
    asm("{ .reg .u64 t; cvta.to.shared.u64 t, %1; cvt.u32.u64 %0, t; }" : "=r"(a) : "l"(p));
    return a;
}

// ===================== pre-round x + weights to tf32 ==========================
struct RoundArgs { const float* s[7]; float* d[7]; int n[7]; };
__global__ void round_all_kernel(RoundArgs ra) {
    int t = blockIdx.y;
    int n4 = ra.n[t] >> 2;
    const float4* s = (const float4*)ra.s[t];
    uint4* d = (uint4*)ra.d[t];
    for (int i = blockIdx.x * blockDim.x + threadIdx.x; i < n4; i += gridDim.x * blockDim.x) {
        float4 v = s[i];
        d[i] = make_uint4(f2tf32(v.x), f2tf32(v.y), f2tf32(v.z), f2tf32(v.w));
    }
}

// ===================== dtype detect (1 warp) ==================================
__global__ void detect_kernel(const int* __restrict__ ei32) {
    int lane = threadIdx.x;
    int nz = 0;
#pragma unroll
    for (int t = 0; t < 32; t++) nz |= ei32[1 + 2 * (lane + 32 * t)];
    unsigned any = __ballot_sync(0xffffffffu, nz != 0);
    if (lane == 0) g_idx64 = (any == 0u);
}

__device__ __forceinline__ int load_idx(const void* ei, long long pos) {
    if (g_idx64) return (int)((const long long*)ei)[pos];
    return ((const int*)ei)[pos];
}

// ===================== CSR build ==============================================
__global__ void zero_counts_kernel() {
    int i = blockIdx.x * blockDim.x + threadIdx.x;
    if (i < N_NODES) { g_deg[i] = 0; g_cur[i] = 0; }
}

__global__ void hist_kernel(const void* __restrict__ ei) {
    int e = blockIdx.x * blockDim.x + threadIdx.x;
    if (e < N_EDGES) {
        int d = load_idx(ei, (long long)N_EDGES + e);
        if ((unsigned)d < (unsigned)N_NODES) atomicAdd(&g_deg[d], 1);
    }
}

// scan pass1: 50 blocks x 1024 threads, 1000 elems/block -> local excl + block sums
__global__ void scan1_kernel() {
    __shared__ int wsum[32];
    int tid = threadIdx.x, b = blockIdx.x;
    int idx = b * 1000 + tid;
    int v = (tid < 1000) ? g_deg[idx] : 0;
    int lane = tid & 31, w = tid >> 5;
    int ix = v;
#pragma unroll
    for (int o = 1; o < 32; o <<= 1) {
        int t = __shfl_up_sync(0xffffffffu, ix, o);
        if (lane >= o) ix += t;
    }
    if (lane == 31) wsum[w] = ix;
    __syncthreads();
    if (w == 0) {
        int t = wsum[lane];
#pragma unroll
        for (int o = 1; o < 32; o <<= 1) {
            int u = __shfl_up_sync(0xffffffffu, t, o);
            if (lane >= o) t += u;
        }
        wsum[lane] = t;
    }
    __syncthreads();
    int excl = ((w > 0) ? wsum[w - 1] : 0) + ix - v;
    if (tid < 1000) g_off[idx] = excl;
    if (tid == 1023) g_bsum[b] = wsum[31];
}

// scan pass2: scan 50 block sums
__global__ void scan2_kernel() {
    __shared__ int s[64];
    int tid = threadIdx.x;
    int v = (tid < 50) ? g_bsum[tid] : 0;
    s[tid] = v;
    __syncthreads();
#pragma unroll
    for (int o = 1; o < 64; o <<= 1) {
        int t = (tid >= o) ? s[tid - o] : 0;
        __syncthreads();
        s[tid] += t;
        __syncthreads();
    }
    if (tid < 50) g_boff[tid] = s[tid] - v;
    if (tid == 63) g_off[N_NODES] = s[63];
}

// scan pass3: add block offsets
__global__ void scan3_kernel() {
    int tid = threadIdx.x, b = blockIdx.x;
    if (tid < 1000) g_off[b * 1000 + tid] += g_boff[b];
}

__global__ void scatter_kernel(const void* __restrict__ ei) {
    int e = blockIdx.x * blockDim.x + threadIdx.x;
    if (e < N_EDGES) {
        int s = load_idx(ei, e);
        int d = load_idx(ei, (long long)N_EDGES + e);
        if ((unsigned)d < (unsigned)N_NODES && (unsigned)s < (unsigned)N_NODES) {
            int pos = atomicAdd(&g_cur[d], 1);
            g_srcs[g_off[d] + pos] = s;
        }
    }
}

// ===================== mean aggregation (warp/node, float4, unroll-2) =========
// writes tf32-rounded output (feeds GEMM raw-bit path)
template <int D>
__global__ void aggregate_kernel(const float* __restrict__ feat,
                                 float* __restrict__ out) {
    int warp = (blockIdx.x * blockDim.x + threadIdx.x) >> 5;
    if (warp >= N_NODES) return;
    int lane = threadIdx.x & 31;
    int beg = g_off[warp];
    int end = g_off[warp + 1];
    constexpr int C = D / 128;

    float4 acc[C];
#pragma unroll
    for (int j = 0; j < C; j++) acc[j] = make_float4(0.f, 0.f, 0.f, 0.f);

    int i = beg;
    for (; i + 1 < end; i += 2) {
        const float4* r0 = (const float4*)(feat + (size_t)g_srcs[i] * D);
        const float4* r1 = (const float4*)(feat + (size_t)g_srcs[i + 1] * D);
#pragma unroll
        for (int j = 0; j < C; j++) {
            float4 a = __ldg(&r0[lane + 32 * j]);
            float4 b = __ldg(&r1[lane + 32 * j]);
            acc[j].x += a.x + b.x; acc[j].y += a.y + b.y;
            acc[j].z += a.z + b.z; acc[j].w += a.w + b.w;
        }
    }
    if (i < end) {
        const float4* r0 = (const float4*)(feat + (size_t)g_srcs[i] * D);
#pragma unroll
        for (int j = 0; j < C; j++) {
            float4 a = __ldg(&r0[lane + 32 * j]);
            acc[j].x += a.x; acc[j].y += a.y; acc[j].z += a.z; acc[j].w += a.w;
        }
    }
    int cnt = end - beg;
    float inv = 1.0f / (float)(cnt > 0 ? cnt : 1);
    uint4* o = (uint4*)(out + (size_t)warp * D);
#pragma unroll
    for (int j = 0; j < C; j++)
        o[lane + 32 * j] = make_uint4(f2tf32(acc[j].x * inv), f2tf32(acc[j].y * inv),
                                      f2tf32(acc[j].z * inv), f2tf32(acc[j].w * inv));
}

// ===================== layer-2 final: out = mean(P[src,0:256]) + P[row,256:512] + b
__global__ void final_agg_kernel(const float* __restrict__ P,
                                 const float* __restrict__ bias,
                                 float* __restrict__ out) {
    int warp = (blockIdx.x * blockDim.x + threadIdx.x) >> 5;
    if (warp >= N_NODES) return;
    int lane = threadIdx.x & 31;
    int beg = g_off[warp];
    int end = g_off[warp + 1];

    float4 acc[2];
#pragma unroll
    for (int j = 0; j < 2; j++) acc[j] = make_float4(0.f, 0.f, 0.f, 0.f);

    int i = beg;
    for (; i + 1 < end; i += 2) {
        const float4* r0 = (const float4*)(P + (size_t)g_srcs[i] * 512);
        const float4* r1 = (const float4*)(P + (size_t)g_srcs[i + 1] * 512);
#pragma unroll
        for (int j = 0; j < 2; j++) {
            float4 a = __ldg(&r0[lane + 32 * j]);
            float4 b = __ldg(&r1[lane + 32 * j]);
            acc[j].x += a.x + b.x; acc[j].y += a.y + b.y;
            acc[j].z += a.z + b.z; acc[j].w += a.w + b.w;
        }
    }
    if (i < end) {
        const float4* r0 = (const float4*)(P + (size_t)g_srcs[i] * 512);
#pragma unroll
        for (int j = 0; j < 2; j++) {
            float4 a = __ldg(&r0[lane + 32 * j]);
            acc[j].x += a.x; acc[j].y += a.y; acc[j].z += a.z; acc[j].w += a.w;
        }
    }
    int cnt = end - beg;
    float inv = 1.0f / (float)(cnt > 0 ? cnt : 1);
    const float4* R = (const float4*)(P + (size_t)warp * 512 + 256);
    const float4* B = (const float4*)bias;
    float4* o = (float4*)(out + (size_t)warp * 256);
#pragma unroll
    for (int j = 0; j < 2; j++) {
        float4 r = R[lane + 32 * j];
        float4 b = B[lane + 32 * j];
        float4 v;
        v.x = acc[j].x * inv + r.x + b.x;
        v.y = acc[j].y * inv + r.y + b.y;
        v.z = acc[j].z * inv + r.z + b.z;
        v.w = acc[j].w * inv + r.w + b.w;
        o[lane + 32 * j] = v;
    }
}

// ===================== tf32 mma.sync GEMM, cp.async 2-stage ===================
// DUAL:  C = A1@W1^T + A2@W2^T (+bias,+relu,+round).  W row-major [N,K].
// !DUAL: C = A1@Wsel^T where Wsel = W1 rows [0,Nsplit) / W2 rows beyond.
// CTA 128x128, BK=32, XOR-swizzled smem (16B chunks), 8 warps 2x4, warp 64x32.
#define GEMM_SMEM 65536

template <bool DUAL, bool RELU, bool ROUND>
__global__ void __launch_bounds__(256)
gemm_mma_kernel(const float* __restrict__ A1, const float* __restrict__ W1,
                const float* __restrict__ A2, const float* __restrict__ W2,
                const float* __restrict__ bias, float* __restrict__ C,
                int M, int N, int K, int Nsplit) {
    extern __shared__ uint32_t sm[];
    uint32_t smb = smem_u32(sm);

    int tid = threadIdx.x, lane = tid & 31, wid = tid >> 5;
    int bm = blockIdx.x * 128, bn = blockIdx.y * 128;
    int wm = wid & 1, wn = wid >> 1;

    const float* Wsel = nullptr;
    if (!DUAL)
        Wsel = (bn < Nsplit) ? W1 + (size_t)bn * K : W2 + (size_t)(bn - Nsplit) * K;

    float acc[4][4][4];
#pragma unroll
    for (int mi = 0; mi < 4; mi++)
#pragma unroll
        for (int ni = 0; ni < 4; ni++)
#pragma unroll
            for (int r = 0; r < 4; r++) acc[mi][ni][r] = 0.0f;

    int chunks = K >> 5;
    int total = DUAL ? 2 * chunks : chunks;

    auto prefetch = [&](int it, int stage) {
        int pass = DUAL ? (it >= chunks) : 0;
        int k0 = ((DUAL && pass) ? it - chunks : it) << 5;
        const float* A = (DUAL && pass) ? A2 : A1;
        uint32_t abase = smb + stage * 32768;
        uint32_t bbase = abase + 16384;
#pragma unroll
        for (int t = 0; t < 4; t++) {
            int idx = tid + t * 256;
            int row = idx >> 3, q = idx & 7;
            uint32_t swz = ((uint32_t)(q ^ (row & 7))) << 4;   // bytes
            int gr = bm + row;
            const float* srcA = A + (size_t)(gr < M ? gr : M - 1) * K + k0 + q * 4;
            cp_async16(abase + row * 128 + swz, srcA, (gr < M) ? 16 : 0);
            const float* srcB;
            if (DUAL) {
                const float* W = pass ? W2 : W1;
                srcB = W + (size_t)(bn + row) * K + k0 + q * 4;
            } else {
                srcB = Wsel + (size_t)row * K + k0 + q * 4;
            }
            cp_async16(bbase + row * 128 + swz, srcB, 16);
        }
    };

    prefetch(0, 0);
    CP_COMMIT();

    int qr = lane >> 2, qc = lane & 3;
    for (int it = 0; it < total; it++) {
        if (it + 1 < total) prefetch(it + 1, (it + 1) & 1);
        CP_COMMIT();
        CP_WAIT1();
        __syncthreads();

        const uint32_t* as = sm + (it & 1) * 8192;
        const uint32_t* bs = as + 4096;
#pragma unroll
        for (int ka = 0; ka < 4; ka++) {
            uint32_t sw0 = (uint32_t)(((2 * ka) ^ qr) << 2) + qc;
            uint32_t sw1 = (uint32_t)(((2 * ka + 1) ^ qr) << 2) + qc;
            uint32_t a[4][4], b[4][2];
#pragma unroll
            for (int mi = 0; mi < 4; mi++) {
                int r0 = wm * 64 + mi * 16 + qr;
                a[mi][0] = as[r0 * 32 + sw0];
                a[mi][1] = as[(r0 + 8) * 32 + sw0];
                a[mi][2] = as[r0 * 32 + sw1];
                a[mi][3] = as[(r0 + 8) * 32 + sw1];
            }
#pragma unroll
            for (int ni = 0; ni < 4; ni++) {
                int c0 = wn * 32 + ni * 8 + qr;
                b[ni][0] = bs[c0 * 32 + sw0];
                b[ni][1] = bs[c0 * 32 + sw1];
            }
#pragma unroll
            for (int mi = 0; mi < 4; mi++)
#pragma unroll
                for (int ni = 0; ni < 4; ni++)
                    mma_tf32(acc[mi][ni], a[mi], b[ni]);
        }
        __syncthreads();
    }

    int qc2 = (lane & 3) * 2;
#pragma unroll
    for (int mi = 0; mi < 4; mi++) {
#pragma unroll
        for (int half = 0; half < 2; half++) {
            int row = bm + wm * 64 + mi * 16 + qr + half * 8;
            if (row >= M) continue;
#pragma unroll
            for (int ni = 0; ni < 4; ni++) {
                int col = bn + wn * 32 + ni * 8 + qc2;
                float2 o;
                o.x = acc[mi][ni][half * 2 + 0];
                o.y = acc[mi][ni][half * 2 + 1];
                if (bias) { o.x += bias[col]; o.y += bias[col + 1]; }
                if (RELU) { o.x = fmaxf(o.x, 0.f); o.y = fmaxf(o.y, 0.f); }
                if (ROUND) { o.x = roundtf(o.x); o.y = roundtf(o.y); }
                *(float2*)(C + (size_t)row * N + col) = o;
            }
        }
    }
}

// ===================== launch ==================================================
extern "C" void kernel_launch(void* const* d_in, const int* in_sizes, int n_in,
                              void* d_out, int out_size) {
    const float* x   = (const float*)d_in[0];
    const void*  ei  = d_in[1];
    const float* Wl0 = (const float*)d_in[2];
    const float* bl0 = (const float*)d_in[3];
    const float* Wr0 = (const float*)d_in[4];
    const float* Wl1 = (const float*)d_in[5];
    const float* bl1 = (const float*)d_in[6];
    const float* Wr1 = (const float*)d_in[7];
    const float* Wl2 = (const float*)d_in[8];
    const float* bl2 = (const float*)d_in[9];
    const float* Wr2 = (const float*)d_in[10];
    float*       out = (float*)d_out;

    int M = in_sizes[0] / 128;   // 50000

    float *agg, *h1, *h2, *xr, *wr;
    cudaGetSymbolAddress((void**)&agg, g_agg);
    cudaGetSymbolAddress((void**)&h1,  g_h1);
    cudaGetSymbolAddress((void**)&h2,  g_h2);
    cudaGetSymbolAddress((void**)&xr,  g_xr);
    cudaGetSymbolAddress((void**)&wr,  g_wr);

    float* wl0r = wr;
    float* wr0r = wr + 65536;
    float* wl1r = wr + 131072;
    float* wr1r = wr + 393216;
    float* wl2r = wr + 655360;
    float* wr2r = wr + 786432;

    cudaFuncSetAttribute(gemm_mma_kernel<true, true, true>,
                         cudaFuncAttributeMaxDynamicSharedMemorySize, GEMM_SMEM);
    cudaFuncSetAttribute(gemm_mma_kernel<false, false, false>,
                         cudaFuncAttributeMaxDynamicSharedMemorySize, GEMM_SMEM);

    // pre-round x + all weights to tf32 (one launch)
    RoundArgs ra;
    ra.s[0] = x;   ra.d[0] = xr;   ra.n[0] = M * 128;
    ra.s[1] = Wl0; ra.d[1] = wl0r; ra.n[1] = 512 * 128;
    ra.s[2] = Wr0; ra.d[2] = wr0r; ra.n[2] = 512 * 128;
    ra.s[3] = Wl1; ra.d[3] = wl1r; ra.n[3] = 512 * 512;
    ra.s[4] = Wr1; ra.d[4] = wr1r; ra.n[4] = 512 * 512;
    ra.s[5] = Wl2; ra.d[5] = wl2r; ra.n[5] = 256 * 512;
    ra.s[6] = Wr2; ra.d[6] = wr2r; ra.n[6] = 256 * 512;
    round_all_kernel<<<dim3(256, 7), 256>>>(ra);

    // CSR build
    detect_kernel<<<1, 32>>>((const int*)ei);
    zero_counts_kernel<<<(N_NODES + 255) / 256, 256>>>();
    hist_kernel<<<(N_EDGES + 255) / 256, 256>>>(ei);
    scan1_kernel<<<50, 1024>>>();
    scan2_kernel<<<1, 64>>>();
    scan3_kernel<<<50, 1024>>>();
    scatter_kernel<<<(N_EDGES + 255) / 256, 256>>>(ei);

    int aggBlocks = (N_NODES * 32 + 255) / 256;
    int mTiles = (M + 127) / 128;

    // Layer 0: 128 -> 512, relu
    aggregate_kernel<128><<<aggBlocks, 256>>>(x, agg);
    gemm_mma_kernel<true, true, true><<<dim3(mTiles, 4), 256, GEMM_SMEM>>>(
        agg, wl0r, xr, wr0r, bl0, h1, M, 512, 128, 0);

    // Layer 1: 512 -> 512, relu
    aggregate_kernel<512><<<aggBlocks, 256>>>(h1, agg);
    gemm_mma_kernel<true, true, true><<<dim3(mTiles, 4), 256, GEMM_SMEM>>>(
        agg, wl1r, h1, wr1r, bl1, h2, M, 512, 512, 0);

    // Layer 2 (projection-first): P|R = h2 @ [Wl2;Wr2]^T  -> then mean(P)+R+b
    gemm_mma_kernel<false, false, false><<<dim3(mTiles, 4), 256, GEMM_SMEM>>>(
        h2, wl2r, nullptr, wr2r, nullptr, agg, M, 512, 512, 256);
    final_agg_kernel<<<aggBlocks, 256>>>(agg, bl2, out);
}

// round 6
// speedup vs baseline: 6.0069x; 1.6510x over previous
#include <cuda_runtime.h>
#include <cuda_fp16.h>
#include <cstdint>

#define N_NODES 50000
#define N_EDGES 800000

// ===================== scratch =================================================
__device__ __half g_aggh[N_NODES * 512];
__device__ __half g_h1h[N_NODES * 512];
__device__ __half g_h2h[N_NODES * 512];
__device__ __half g_xh[N_NODES * 128];
__device__ __half g_wh[917504];
__device__ float  g_P[N_NODES * 512];
__device__ int    g_deg[N_NODES];
__device__ int    g_off[N_NODES + 1];
__device__ int    g_cur[N_NODES];
__device__ int    g_srcs[N_EDGES];
__device__ int    g_bsum[64];
__device__ int    g_boff[64];
__device__ int    g_idx64;

__device__ __forceinline__ void mma_f16(float* c, const uint32_t* a, const uint32_t* b) {
    asm volatile(
        "mma.sync.aligned.m16n8k16.row.col.f32.f16.f16.f32 "
        "{%0,%1,%2,%3}, {%4,%5,%6,%7}, {%8,%9}, {%0,%1,%2,%3};"
        : "+f"(c[0]), "+f"(c[1]), "+f"(c[2]), "+f"(c[3])
        : "r"(a[0]), "r"(a[1]), "r"(a[2]), "r"(a[3]), "r"(b[0]), "r"(b[1]));
}

__device__ __forceinline__ void cp_async16(uint32_t dst, const void* src, int sz) {
    asm volatile("cp.async.cg.shared.global [%0], [%1], 16, %2;"
                 :: "r"(dst), "l"(src), "r"(sz) : "memory");
}
#define CP_COMMIT() asm volatile("cp.async.commit_group;" ::: "memory")
#define CP_WAIT1()  asm volatile("cp.async.wait_group 1;" ::: "memory")

__device__ __forceinline__ uint32_t smem_u32(const void* p) {
    uint32_t a;
    asm("{ .reg .u64 t; cvta.to.shared.u64 t, %1; cvt.u32.u64 %0, t; }" : "=r"(a) : "l"(p));
    return a;
}

__device__ __forceinline__ void acc_u32h2(float2& a, uint32_t u) {
    __half2 h = *reinterpret_cast<__half2*>(&u);
    float2 f = __half22float2(h);
    a.x += f.x; a.y += f.y;
}
__device__ __forceinline__ uint32_t pack_h2(float x, float y) {
    __half2 h = __floats2half2_rn(x, y);
    return *reinterpret_cast<uint32_t*>(&h);
}

// ===================== fp32 -> fp16 conversion (x + weights) =================
struct RoundArgs { const float* s[7]; __half* d[7]; int n[7]; };
__global__ void round_all_kernel(RoundArgs ra) {
    int t = blockIdx.y;
    int n4 = ra.n[t] >> 2;
    const float4* s = (const float4*)ra.s[t];
    uint2* d = (uint2*)ra.d[t];
    for (int i = blockIdx.x * blockDim.x + threadIdx.x; i < n4; i += gridDim.x * blockDim.x) {
        float4 v = s[i];
        d[i] = make_uint2(pack_h2(v.x, v.y), pack_h2(v.z, v.w));
    }
}

// ===================== dtype detect (1 warp) ==================================
__global__ void detect_kernel(const int* __restrict__ ei32) {
    int lane = threadIdx.x;
    int nz = 0;
#pragma unroll
    for (int t = 0; t < 32; t++) nz |= ei32[1 + 2 * (lane + 32 * t)];
    unsigned any = __ballot_sync(0xffffffffu, nz != 0);
    if (lane == 0) g_idx64 = (any == 0u);
}

__device__ __forceinline__ int load_idx(const void* ei, long long pos) {
    if (g_idx64) return (int)((const long long*)ei)[pos];
    return ((const int*)ei)[pos];
}

// ===================== CSR build ==============================================
__global__ void zero_counts_kernel() {
    int i = blockIdx.x * blockDim.x + threadIdx.x;
    if (i < N_NODES) { g_deg[i] = 0; g_cur[i] = 0; }
}

__global__ void hist_kernel(const void* __restrict__ ei) {
    int e = blockIdx.x * blockDim.x + threadIdx.x;
    if (e < N_EDGES) {
        int d = load_idx(ei, (long long)N_EDGES + e);
        if ((unsigned)d < (unsigned)N_NODES) atomicAdd(&g_deg[d], 1);
    }
}

__global__ void scan1_kernel() {
    __shared__ int wsum[32];
    int tid = threadIdx.x, b = blockIdx.x;
    int idx = b * 1000 + tid;
    int v = (tid < 1000) ? g_deg[idx] : 0;
    int lane = tid & 31, w = tid >> 5;
    int ix = v;
#pragma unroll
    for (int o = 1; o < 32; o <<= 1) {
        int t = __shfl_up_sync(0xffffffffu, ix, o);
        if (lane >= o) ix += t;
    }
    if (lane == 31) wsum[w] = ix;
    __syncthreads();
    if (w == 0) {
        int t = wsum[lane];
#pragma unroll
        for (int o = 1; o < 32; o <<= 1) {
            int u = __shfl_up_sync(0xffffffffu, t, o);
            if (lane >= o) t += u;
        }
        wsum[lane] = t;
    }
    __syncthreads();
    int excl = ((w > 0) ? wsum[w - 1] : 0) + ix - v;
    if (tid < 1000) g_off[idx] = excl;
    if (tid == 1023) g_bsum[b] = wsum[31];
}

__global__ void scan2_kernel() {
    __shared__ int s[64];
    int tid = threadIdx.x;
    int v = (tid < 50) ? g_bsum[tid] : 0;
    s[tid] = v;
    __syncthreads();
#pragma unroll
    for (int o = 1; o < 64; o <<= 1) {
        int t = (tid >= o) ? s[tid - o] : 0;
        __syncthreads();
        s[tid] += t;
        __syncthreads();
    }
    if (tid < 50) g_boff[tid] = s[tid] - v;
    if (tid == 63) g_off[N_NODES] = s[63];
}

__global__ void scan3_kernel() {
    int tid = threadIdx.x, b = blockIdx.x;
    if (tid < 1000) g_off[b * 1000 + tid] += g_boff[b];
}

__global__ void scatter_kernel(const void* __restrict__ ei) {
    int e = blockIdx.x * blockDim.x + threadIdx.x;
    if (e < N_EDGES) {
        int s = load_idx(ei, e);
        int d = load_idx(ei, (long long)N_EDGES + e);
        if ((unsigned)d < (unsigned)N_NODES && (unsigned)s < (unsigned)N_NODES) {
            int pos = atomicAdd(&g_cur[d], 1);
            g_srcs[g_off[d] + pos] = s;
        }
    }
}

// ===================== fp16 mean aggregation (warp/node) ======================
template <int D>
__global__ void aggregate_kernel(const __half* __restrict__ feat,
                                 __half* __restrict__ out) {
    int warp = (blockIdx.x * blockDim.x + threadIdx.x) >> 5;
    if (warp >= N_NODES) return;
    int lane = threadIdx.x & 31;
    int beg = g_off[warp];
    int end = g_off[warp + 1];

    if (D == 512) {
        float2 acc[8];
#pragma unroll
        for (int j = 0; j < 8; j++) acc[j] = make_float2(0.f, 0.f);
        int i = beg;
        for (; i + 1 < end; i += 2) {
            const uint4* r0 = (const uint4*)(feat + (size_t)g_srcs[i] * 512);
            const uint4* r1 = (const uint4*)(feat + (size_t)g_srcs[i + 1] * 512);
#pragma unroll
            for (int c = 0; c < 2; c++) {
                uint4 v0 = __ldg(&r0[lane + 32 * c]);
                uint4 v1 = __ldg(&r1[lane + 32 * c]);
                acc_u32h2(acc[4 * c + 0], v0.x); acc_u32h2(acc[4 * c + 0], v1.x);
                acc_u32h2(acc[4 * c + 1], v0.y); acc_u32h2(acc[4 * c + 1], v1.y);
                acc_u32h2(acc[4 * c + 2], v0.z); acc_u32h2(acc[4 * c + 2], v1.z);
                acc_u32h2(acc[4 * c + 3], v0.w); acc_u32h2(acc[4 * c + 3], v1.w);
            }
        }
        if (i < end) {
            const uint4* r0 = (const uint4*)(feat + (size_t)g_srcs[i] * 512);
#pragma unroll
            for (int c = 0; c < 2; c++) {
                uint4 v0 = __ldg(&r0[lane + 32 * c]);
                acc_u32h2(acc[4 * c + 0], v0.x);
                acc_u32h2(acc[4 * c + 1], v0.y);
                acc_u32h2(acc[4 * c + 2], v0.z);
                acc_u32h2(acc[4 * c + 3], v0.w);
            }
        }
        int cnt = end - beg;
        float inv = 1.0f / (float)(cnt > 0 ? cnt : 1);
        uint4* o = (uint4*)(out + (size_t)warp * 512);
#pragma unroll
        for (int c = 0; c < 2; c++) {
            uint4 v;
            v.x = pack_h2(acc[4 * c + 0].x * inv, acc[4 * c + 0].y * inv);
            v.y = pack_h2(acc[4 * c + 1].x * inv, acc[4 * c + 1].y * inv);
            v.z = pack_h2(acc[4 * c + 2].x * inv, acc[4 * c + 2].y * inv);
            v.w = pack_h2(acc[4 * c + 3].x * inv, acc[4 * c + 3].y * inv);
            o[lane + 32 * c] = v;
        }
    } else {  // D == 128: lane owns 4 halves (one uint2)
        float2 acc[2];
        acc[0] = make_float2(0.f, 0.f); acc[1] = make_float2(0.f, 0.f);
        int i = beg;
        for (; i + 1 < end; i += 2) {
            uint2 v0 = __ldg((const uint2*)(feat + (size_t)g_srcs[i] * 128) + lane);
            uint2 v1 = __ldg((const uint2*)(feat + (size_t)g_srcs[i + 1] * 128) + lane);
            acc_u32h2(acc[0], v0.x); acc_u32h2(acc[0], v1.x);
            acc_u32h2(acc[1], v0.y); acc_u32h2(acc[1], v1.y);
        }
        if (i < end) {
            uint2 v0 = __ldg((const uint2*)(feat + (size_t)g_srcs[i] * 128) + lane);
            acc_u32h2(acc[0], v0.x);
            acc_u32h2(acc[1], v0.y);
        }
        int cnt = end - beg;
        float inv = 1.0f / (float)(cnt > 0 ? cnt : 1);
        uint2 v;
        v.x = pack_h2(acc[0].x * inv, acc[0].y * inv);
        v.y = pack_h2(acc[1].x * inv, acc[1].y * inv);
        *((uint2*)(out + (size_t)warp * 128) + lane) = v;
    }
}

// ===================== layer-2 final: out = mean(P[src,0:256]) + P[row,256:512] + b
__global__ void final_agg_kernel(const float* __restrict__ P,
                                 const float* __restrict__ bias,
                                 float* __restrict__ out) {
    int warp = (blockIdx.x * blockDim.x + threadIdx.x) >> 5;
    if (warp >= N_NODES) return;
    int lane = threadIdx.x & 31;
    int beg = g_off[warp];
    int end = g_off[warp + 1];

    float4 acc[2];
#pragma unroll
    for (int j = 0; j < 2; j++) acc[j] = make_float4(0.f, 0.f, 0.f, 0.f);

    int i = beg;
    for (; i + 1 < end; i += 2) {
        const float4* r0 = (const float4*)(P + (size_t)g_srcs[i] * 512);
        const float4* r1 = (const float4*)(P + (size_t)g_srcs[i + 1] * 512);
#pragma unroll
        for (int j = 0; j < 2; j++) {
            float4 a = __ldg(&r0[lane + 32 * j]);
            float4 b = __ldg(&r1[lane + 32 * j]);
            acc[j].x += a.x + b.x; acc[j].y += a.y + b.y;
            acc[j].z += a.z + b.z; acc[j].w += a.w + b.w;
        }
    }
    if (i < end) {
        const float4* r0 = (const float4*)(P + (size_t)g_srcs[i] * 512);
#pragma unroll
        for (int j = 0; j < 2; j++) {
            float4 a = __ldg(&r0[lane + 32 * j]);
            acc[j].x += a.x; acc[j].y += a.y; acc[j].z += a.z; acc[j].w += a.w;
        }
    }
    int cnt = end - beg;
    float inv = 1.0f / (float)(cnt > 0 ? cnt : 1);
    const float4* R = (const float4*)(P + (size_t)warp * 512 + 256);
    const float4* B = (const float4*)bias;
    float4* o = (float4*)(out + (size_t)warp * 256);
#pragma unroll
    for (int j = 0; j < 2; j++) {
        float4 r = R[lane + 32 * j];
        float4 b = B[lane + 32 * j];
        float4 v;
        v.x = acc[j].x * inv + r.x + b.x;
        v.y = acc[j].y * inv + r.y + b.y;
        v.z = acc[j].z * inv + r.z + b.z;
        v.w = acc[j].w * inv + r.w + b.w;
        o[lane + 32 * j] = v;
    }
}

// ===================== fp16 mma GEMM, cp.async 2-stage, BK=64 =================
// DUAL:  C = A1@W1^T + A2@W2^T (+bias,+relu).  W row-major [N,K] fp16.
// !DUAL: C = A1@Wsel^T, Wsel picked by bn vs Nsplit. OUTHALF: fp16 C else fp32.
// CTA 128x128, BK=64 (128B rows, XOR-swizzled 16B granules), 8 warps 2x4.
#define GEMM_SMEM 65536

template <bool DUAL, bool RELU, bool OUTHALF>
__global__ void __launch_bounds__(256)
gemm_h_kernel(const __half* __restrict__ A1, const __half* __restrict__ W1,
              const __half* __restrict__ A2, const __half* __restrict__ W2,
              const float* __restrict__ bias, void* __restrict__ Cout,
              int M, int N, int K, int Nsplit) {
    extern __shared__ uint32_t sm[];
    uint32_t smb = smem_u32(sm);

    int tid = threadIdx.x, lane = tid & 31, wid = tid >> 5;
    int bm = blockIdx.x * 128, bn = blockIdx.y * 128;
    int wm = wid & 1, wn = wid >> 1;

    const __half* Wsel = nullptr;
    if (!DUAL)
        Wsel = (bn < Nsplit) ? W1 + (size_t)bn * K : W2 + (size_t)(bn - Nsplit) * K;

    float acc[4][4][4];
#pragma unroll
    for (int mi = 0; mi < 4; mi++)
#pragma unroll
        for (int ni = 0; ni < 4; ni++)
#pragma unroll
            for (int r = 0; r < 4; r++) acc[mi][ni][r] = 0.0f;

    int chunks = K >> 6;                 // BK = 64 halves
    int total = DUAL ? 2 * chunks : chunks;

    auto prefetch = [&](int it, int stage) {
        int pass = DUAL ? (it >= chunks) : 0;
        int k0 = ((DUAL && pass) ? it - chunks : it) << 6;
        const __half* A = (DUAL && pass) ? A2 : A1;
        uint32_t abase = smb + stage * 32768;
        uint32_t bbase = abase + 16384;
#pragma unroll
        for (int t = 0; t < 4; t++) {
            int idx = tid + t * 256;
            int row = idx >> 3, q = idx & 7;
            uint32_t swz = (uint32_t)(q ^ (row & 7)) << 4;  // bytes
            int gr = bm + row;
            const __half* srcA = A + (size_t)(gr < M ? gr : 0) * K + k0 + q * 8;
            cp_async16(abase + row * 128 + swz, srcA, (gr < M) ? 16 : 0);
            const __half* srcB;
            if (DUAL) {
                const __half* W = pass ? W2 : W1;
                srcB = W + (size_t)(bn + row) * K + k0 + q * 8;
            } else {
                srcB = Wsel + (size_t)row * K + k0 + q * 8;
            }
            cp_async16(bbase + row * 128 + swz, srcB, 16);
        }
    };

    prefetch(0, 0);
    CP_COMMIT();

    int qr = lane >> 2, qc = lane & 3;
    for (int it = 0; it < total; it++) {
        if (it + 1 < total) prefetch(it + 1, (it + 1) & 1);
        CP_COMMIT();
        CP_WAIT1();
        __syncthreads();

        const uint32_t* as = sm + (it & 1) * 8192;   // 32 words/row, 128 rows
        const uint32_t* bs = as + 4096;
#pragma unroll
        for (int ks = 0; ks < 4; ks++) {
            int g0 = 2 * ks, g1 = 2 * ks + 1;
            uint32_t a[4][4], b[4][2];
#pragma unroll
            for (int mi = 0; mi < 4; mi++) {
                int r0 = wm * 64 + mi * 16 + qr, r1 = r0 + 8;
                a[mi][0] = as[r0 * 32 + ((g0 ^ (r0 & 7)) << 2) + qc];
                a[mi][1] = as[r1 * 32 + ((g0 ^ (r1 & 7)) << 2) + qc];
                a[mi][2] = as[r0 * 32 + ((g1 ^ (r0 & 7)) << 2) + qc];
                a[mi][3] = as[r1 * 32 + ((g1 ^ (r1 & 7)) << 2) + qc];
            }
#pragma unroll
            for (int ni = 0; ni < 4; ni++) {
                int n0 = wn * 32 + ni * 8 + qr;
                b[ni][0] = bs[n0 * 32 + ((g0 ^ (n0 & 7)) << 2) + qc];
                b[ni][1] = bs[n0 * 32 + ((g1 ^ (n0 & 7)) << 2) + qc];
            }
#pragma unroll
            for (int mi = 0; mi < 4; mi++)
#pragma unroll
                for (int ni = 0; ni < 4; ni++)
                    mma_f16(acc[mi][ni], a[mi], b[ni]);
        }
        __syncthreads();
    }

    int qc2 = (lane & 3) * 2;
#pragma unroll
    for (int mi = 0; mi < 4; mi++) {
#pragma unroll
        for (int half = 0; half < 2; half++) {
            int row = bm + wm * 64 + mi * 16 + qr + half * 8;
            if (row >= M) continue;
#pragma unroll
            for (int ni = 0; ni < 4; ni++) {
                int col = bn + wn * 32 + ni * 8 + qc2;
                float ox = acc[mi][ni][half * 2 + 0];
                float oy = acc[mi][ni][half * 2 + 1];
                if (bias) { ox += bias[col]; oy += bias[col + 1]; }
                if (RELU) { ox = fmaxf(ox, 0.f); oy = fmaxf(oy, 0.f); }
                if (OUTHALF) {
                    *(uint32_t*)((__half*)Cout + (size_t)row * N + col) = pack_h2(ox, oy);
                } else {
                    *(float2*)((float*)Cout + (size_t)row * N + col) = make_float2(ox, oy);
                }
            }
        }
    }
}

// ===================== launch ==================================================
extern "C" void kernel_launch(void* const* d_in, const int* in_sizes, int n_in,
                              void* d_out, int out_size) {
    const float* x   = (const float*)d_in[0];
    const void*  ei  = d_in[1];
    const float* Wl0 = (const float*)d_in[2];
    const float* bl0 = (const float*)d_in[3];
    const float* Wr0 = (const float*)d_in[4];
    const float* Wl1 = (const float*)d_in[5];
    const float* bl1 = (const float*)d_in[6];
    const float* Wr1 = (const float*)d_in[7];
    const float* Wl2 = (const float*)d_in[8];
    const float* bl2 = (const float*)d_in[9];
    const float* Wr2 = (const float*)d_in[10];
    float*       out = (float*)d_out;

    int M = in_sizes[0] / 128;   // 50000

    __half *aggh, *h1h, *h2h, *xh, *wh;
    float* P;
    cudaGetSymbolAddress((void**)&aggh, g_aggh);
    cudaGetSymbolAddress((void**)&h1h,  g_h1h);
    cudaGetSymbolAddress((void**)&h2h,  g_h2h);
    cudaGetSymbolAddress((void**)&xh,   g_xh);
    cudaGetSymbolAddress((void**)&wh,   g_wh);
    cudaGetSymbolAddress((void**)&P,    g_P);

    __half* wl0h = wh;
    __half* wr0h = wh + 65536;
    __half* wl1h = wh + 131072;
    __half* wr1h = wh + 393216;
    __half* wl2h = wh + 655360;
    __half* wr2h = wh + 786432;

    cudaFuncSetAttribute(gemm_h_kernel<true, true, true>,
                         cudaFuncAttributeMaxDynamicSharedMemorySize, GEMM_SMEM);
    cudaFuncSetAttribute(gemm_h_kernel<false, false, false>,
                         cudaFuncAttributeMaxDynamicSharedMemorySize, GEMM_SMEM);

    // convert x + weights to fp16 (one launch)
    RoundArgs ra;
    ra.s[0] = x;   ra.d[0] = xh;   ra.n[0] = M * 128;
    ra.s[1] = Wl0; ra.d[1] = wl0h; ra.n[1] = 512 * 128;
    ra.s[2] = Wr0; ra.d[2] = wr0h; ra.n[2] = 512 * 128;
    ra.s[3] = Wl1; ra.d[3] = wl1h; ra.n[3] = 512 * 512;
    ra.s[4] = Wr1; ra.d[4] = wr1h; ra.n[4] = 512 * 512;
    ra.s[5] = Wl2; ra.d[5] = wl2h; ra.n[5] = 256 * 512;
    ra.s[6] = Wr2; ra.d[6] = wr2h; ra.n[6] = 256 * 512;
    round_all_kernel<<<dim3(256, 7), 256>>>(ra);

    // CSR build
    detect_kernel<<<1, 32>>>((const int*)ei);
    zero_counts_kernel<<<(N_NODES + 255) / 256, 256>>>();
    hist_kernel<<<(N_EDGES + 255) / 256, 256>>>(ei);
    scan1_kernel<<<50, 1024>>>();
    scan2_kernel<<<1, 64>>>();
    scan3_kernel<<<50, 1024>>>();
    scatter_kernel<<<(N_EDGES + 255) / 256, 256>>>(ei);

    int aggBlocks = (N_NODES * 32 + 255) / 256;
    int mTiles = (M + 127) / 128;

    // Layer 0: 128 -> 512, relu
    aggregate_kernel<128><<<aggBlocks, 256>>>(xh, aggh);
    gemm_h_kernel<true, true, true><<<dim3(mTiles, 4), 256, GEMM_SMEM>>>(
        aggh, wl0h, xh, wr0h, bl0, h1h, M, 512, 128, 0);

    // Layer 1: 512 -> 512, relu
    aggregate_kernel<512><<<aggBlocks, 256>>>(h1h, aggh);
    gemm_h_kernel<true, true, true><<<dim3(mTiles, 4), 256, GEMM_SMEM>>>(
        aggh, wl1h, h1h, wr1h, bl1, h2h, M, 512, 512, 0);

    // Layer 2 (projection-first): P|R = h2 @ [Wl2;Wr2]^T (fp32 out), then mean(P)+R+b
    gemm_h_kernel<false, false, false><<<dim3(mTiles, 4), 256, GEMM_SMEM>>>(
        h2h, wl2h, nullptr, wr2h, nullptr, P, M, 512, 512, 256);
    final_agg_kernel<<<aggBlocks, 256>>>(P, bl2, out);
}

// round 7
// speedup vs baseline: 6.3960x; 1.0648x over previous
#include <cuda_runtime.h>
#include <cuda_fp16.h>
#include <cstdint>

#define N_NODES 50000
#define N_EDGES 800000

// ===================== scratch =================================================
__device__ __half g_aggh[N_NODES * 512];
__device__ __half g_h1h[N_NODES * 512];
__device__ __half g_h2h[N_NODES * 512];
__device__ __half g_xh[N_NODES * 128];
__device__ __half g_wh[917504];
__device__ __half g_Pl[N_NODES * 256];
__device__ float  g_Pr[N_NODES * 256];
__device__ int    g_deg[N_NODES];
__device__ int    g_off[N_NODES + 1];
__device__ int    g_cur[N_NODES];
__device__ int    g_srcs[N_EDGES];
__device__ int    g_bsum[64];
__device__ int    g_boff[64];
__device__ int    g_idx64;

__device__ __forceinline__ void mma_f16(float* c, const uint32_t* a, const uint32_t* b) {
    asm volatile(
        "mma.sync.aligned.m16n8k16.row.col.f32.f16.f16.f32 "
        "{%0,%1,%2,%3}, {%4,%5,%6,%7}, {%8,%9}, {%0,%1,%2,%3};"
        : "+f"(c[0]), "+f"(c[1]), "+f"(c[2]), "+f"(c[3])
        : "r"(a[0]), "r"(a[1]), "r"(a[2]), "r"(a[3]), "r"(b[0]), "r"(b[1]));
}

__device__ __forceinline__ void ldsm_x4(uint32_t* r, uint32_t addr) {
    asm volatile("ldmatrix.sync.aligned.m8n8.x4.shared.b16 {%0,%1,%2,%3}, [%4];"
                 : "=r"(r[0]), "=r"(r[1]), "=r"(r[2]), "=r"(r[3]) : "r"(addr));
}
__device__ __forceinline__ void ldsm_x2(uint32_t* r, uint32_t addr) {
    asm volatile("ldmatrix.sync.aligned.m8n8.x2.shared.b16 {%0,%1}, [%2];"
                 : "=r"(r[0]), "=r"(r[1]) : "r"(addr));
}

__device__ __forceinline__ void cp_async16(uint32_t dst, const void* src, int sz) {
    asm volatile("cp.async.cg.shared.global [%0], [%1], 16, %2;"
                 :: "r"(dst), "l"(src), "r"(sz) : "memory");
}
#define CP_COMMIT() asm volatile("cp.async.commit_group;" ::: "memory")
#define CP_WAIT1()  asm volatile("cp.async.wait_group 1;" ::: "memory")

__device__ __forceinline__ uint32_t smem_u32(const void* p) {
    uint32_t a;
    asm("{ .reg .u64 t; cvta.to.shared.u64 t, %1; cvt.u32.u64 %0, t; }" : "=r"(a) : "l"(p));
    return a;
}

__device__ __forceinline__ void acc_u32h2(float2& a, uint32_t u) {
    __half2 h = *reinterpret_cast<__half2*>(&u);
    float2 f = __half22float2(h);
    a.x += f.x; a.y += f.y;
}
__device__ __forceinline__ uint32_t pack_h2(float x, float y) {
    __half2 h = __floats2half2_rn(x, y);
    return *reinterpret_cast<uint32_t*>(&h);
}

// ===================== fp32 -> fp16 conversion (x + weights) =================
struct RoundArgs { const float* s[7]; __half* d[7]; int n[7]; };
__global__ void round_all_kernel(RoundArgs ra) {
    int t = blockIdx.y;
    int n4 = ra.n[t] >> 2;
    const float4* s = (const float4*)ra.s[t];
    uint2* d = (uint2*)ra.d[t];
    for (int i = blockIdx.x * blockDim.x + threadIdx.x; i < n4; i += gridDim.x * blockDim.x) {
        float4 v = s[i];
        d[i] = make_uint2(pack_h2(v.x, v.y), pack_h2(v.z, v.w));
    }
}

// ===================== dtype detect (1 warp) ==================================
__global__ void detect_kernel(const int* __restrict__ ei32) {
    int lane = threadIdx.x;
    int nz = 0;
#pragma unroll
    for (int t = 0; t < 32; t++) nz |= ei32[1 + 2 * (lane + 32 * t)];
    unsigned any = __ballot_sync(0xffffffffu, nz != 0);
    if (lane == 0) g_idx64 = (any == 0u);
}

__device__ __forceinline__ int load_idx(const void* ei, long long pos) {
    if (g_idx64) return (int)((const long long*)ei)[pos];
    return ((const int*)ei)[pos];
}

// ===================== CSR build ==============================================
__global__ void zero_counts_kernel() {
    int i = blockIdx.x * blockDim.x + threadIdx.x;
    if (i < N_NODES) { g_deg[i] = 0; g_cur[i] = 0; }
}

__global__ void hist_kernel(const void* __restrict__ ei) {
    int e = blockIdx.x * blockDim.x + threadIdx.x;
    if (e < N_EDGES) {
        int d = load_idx(ei, (long long)N_EDGES + e);
        if ((unsigned)d < (unsigned)N_NODES) atomicAdd(&g_deg[d], 1);
    }
}

__global__ void scan1_kernel() {
    __shared__ int wsum[32];
    int tid = threadIdx.x, b = blockIdx.x;
    int idx = b * 1000 + tid;
    int v = (tid < 1000) ? g_deg[idx] : 0;
    int lane = tid & 31, w = tid >> 5;
    int ix = v;
#pragma unroll
    for (int o = 1; o < 32; o <<= 1) {
        int t = __shfl_up_sync(0xffffffffu, ix, o);
        if (lane >= o) ix += t;
    }
    if (lane == 31) wsum[w] = ix;
    __syncthreads();
    if (w == 0) {
        int t = wsum[lane];
#pragma unroll
        for (int o = 1; o < 32; o <<= 1) {
            int u = __shfl_up_sync(0xffffffffu, t, o);
            if (lane >= o) t += u;
        }
        wsum[lane] = t;
    }
    __syncthreads();
    int excl = ((w > 0) ? wsum[w - 1] : 0) + ix - v;
    if (tid < 1000) g_off[idx] = excl;
    if (tid == 1023) g_bsum[b] = wsum[31];
}

__global__ void scan2_kernel() {
    __shared__ int s[64];
    int tid = threadIdx.x;
    int v = (tid < 50) ? g_bsum[tid] : 0;
    s[tid] = v;
    __syncthreads();
#pragma unroll
    for (int o = 1; o < 64; o <<= 1) {
        int t = (tid >= o) ? s[tid - o] : 0;
        __syncthreads();
        s[tid] += t;
        __syncthreads();
    }
    if (tid < 50) g_boff[tid] = s[tid] - v;
    if (tid == 63) g_off[N_NODES] = s[63];
}

__global__ void scan3_kernel() {
    int tid = threadIdx.x, b = blockIdx.x;
    if (tid < 1000) g_off[b * 1000 + tid] += g_boff[b];
}

__global__ void scatter_kernel(const void* __restrict__ ei) {
    int e = blockIdx.x * blockDim.x + threadIdx.x;
    if (e < N_EDGES) {
        int s = load_idx(ei, e);
        int d = load_idx(ei, (long long)N_EDGES + e);
        if ((unsigned)d < (unsigned)N_NODES && (unsigned)s < (unsigned)N_NODES) {
            int pos = atomicAdd(&g_cur[d], 1);
            g_srcs[g_off[d] + pos] = s;
        }
    }
}

// ===================== fp16 mean aggregation (warp/node) ======================
template <int D>
__global__ void aggregate_kernel(const __half* __restrict__ feat,
                                 __half* __restrict__ out) {
    int warp = (blockIdx.x * blockDim.x + threadIdx.x) >> 5;
    if (warp >= N_NODES) return;
    int lane = threadIdx.x & 31;
    int beg = g_off[warp];
    int end = g_off[warp + 1];

    if (D == 512) {
        float2 acc[8];
#pragma unroll
        for (int j = 0; j < 8; j++) acc[j] = make_float2(0.f, 0.f);
        int i = beg;
        for (; i + 1 < end; i += 2) {
            const uint4* r0 = (const uint4*)(feat + (size_t)g_srcs[i] * 512);
            const uint4* r1 = (const uint4*)(feat + (size_t)g_srcs[i + 1] * 512);
#pragma unroll
            for (int c = 0; c < 2; c++) {
                uint4 v0 = __ldg(&r0[lane + 32 * c]);
                uint4 v1 = __ldg(&r1[lane + 32 * c]);
                acc_u32h2(acc[4 * c + 0], v0.x); acc_u32h2(acc[4 * c + 0], v1.x);
                acc_u32h2(acc[4 * c + 1], v0.y); acc_u32h2(acc[4 * c + 1], v1.y);
                acc_u32h2(acc[4 * c + 2], v0.z); acc_u32h2(acc[4 * c + 2], v1.z);
                acc_u32h2(acc[4 * c + 3], v0.w); acc_u32h2(acc[4 * c + 3], v1.w);
            }
        }
        if (i < end) {
            const uint4* r0 = (const uint4*)(feat + (size_t)g_srcs[i] * 512);
#pragma unroll
            for (int c = 0; c < 2; c++) {
                uint4 v0 = __ldg(&r0[lane + 32 * c]);
                acc_u32h2(acc[4 * c + 0], v0.x);
                acc_u32h2(acc[4 * c + 1], v0.y);
                acc_u32h2(acc[4 * c + 2], v0.z);
                acc_u32h2(acc[4 * c + 3], v0.w);
            }
        }
        int cnt = end - beg;
        float inv = 1.0f / (float)(cnt > 0 ? cnt : 1);
        uint4* o = (uint4*)(out + (size_t)warp * 512);
#pragma unroll
        for (int c = 0; c < 2; c++) {
            uint4 v;
            v.x = pack_h2(acc[4 * c + 0].x * inv, acc[4 * c + 0].y * inv);
            v.y = pack_h2(acc[4 * c + 1].x * inv, acc[4 * c + 1].y * inv);
            v.z = pack_h2(acc[4 * c + 2].x * inv, acc[4 * c + 2].y * inv);
            v.w = pack_h2(acc[4 * c + 3].x * inv, acc[4 * c + 3].y * inv);
            o[lane + 32 * c] = v;
        }
    } else {  // D == 128
        float2 acc[2];
        acc[0] = make_float2(0.f, 0.f); acc[1] = make_float2(0.f, 0.f);
        int i = beg;
        for (; i + 1 < end; i += 2) {
            uint2 v0 = __ldg((const uint2*)(feat + (size_t)g_srcs[i] * 128) + lane);
            uint2 v1 = __ldg((const uint2*)(feat + (size_t)g_srcs[i + 1] * 128) + lane);
            acc_u32h2(acc[0], v0.x); acc_u32h2(acc[0], v1.x);
            acc_u32h2(acc[1], v0.y); acc_u32h2(acc[1], v1.y);
        }
        if (i < end) {
            uint2 v0 = __ldg((const uint2*)(feat + (size_t)g_srcs[i] * 128) + lane);
            acc_u32h2(acc[0], v0.x);
            acc_u32h2(acc[1], v0.y);
        }
        int cnt = end - beg;
        float inv = 1.0f / (float)(cnt > 0 ? cnt : 1);
        uint2 v;
        v.x = pack_h2(acc[0].x * inv, acc[0].y * inv);
        v.y = pack_h2(acc[1].x * inv, acc[1].y * inv);
        *((uint2*)(out + (size_t)warp * 128) + lane) = v;
    }
}

// ===================== layer-2 final: out = mean(Pl[src]) + Pr[row] + b ========
// Pl fp16 [M,256] (lane owns contiguous 8 elems), Pr fp32 [M,256].
__global__ void final_agg_kernel(const __half* __restrict__ Pl,
                                 const float* __restrict__ Pr,
                                 const float* __restrict__ bias,
                                 float* __restrict__ out) {
    int warp = (blockIdx.x * blockDim.x + threadIdx.x) >> 5;
    if (warp >= N_NODES) return;
    int lane = threadIdx.x & 31;
    int beg = g_off[warp];
    int end = g_off[warp + 1];

    float2 acc[4];
#pragma unroll
    for (int j = 0; j < 4; j++) acc[j] = make_float2(0.f, 0.f);

    int i = beg;
    for (; i + 1 < end; i += 2) {
        uint4 v0 = __ldg((const uint4*)(Pl + (size_t)g_srcs[i] * 256) + lane);
        uint4 v1 = __ldg((const uint4*)(Pl + (size_t)g_srcs[i + 1] * 256) + lane);
        acc_u32h2(acc[0], v0.x); acc_u32h2(acc[0], v1.x);
        acc_u32h2(acc[1], v0.y); acc_u32h2(acc[1], v1.y);
        acc_u32h2(acc[2], v0.z); acc_u32h2(acc[2], v1.z);
        acc_u32h2(acc[3], v0.w); acc_u32h2(acc[3], v1.w);
    }
    if (i < end) {
        uint4 v0 = __ldg((const uint4*)(Pl + (size_t)g_srcs[i] * 256) + lane);
        acc_u32h2(acc[0], v0.x);
        acc_u32h2(acc[1], v0.y);
        acc_u32h2(acc[2], v0.z);
        acc_u32h2(acc[3], v0.w);
    }
    int cnt = end - beg;
    float inv = 1.0f / (float)(cnt > 0 ? cnt : 1);
    const float4* pr = (const float4*)(Pr + (size_t)warp * 256 + lane * 8);
    const float4* bb = (const float4*)(bias + lane * 8);
    float4* o = (float4*)(out + (size_t)warp * 256 + lane * 8);
    float4 r0 = __ldg(&pr[0]), r1 = __ldg(&pr[1]);
    float4 b0 = bb[0], b1 = bb[1];
    float4 v0, v1;
    v0.x = acc[0].x * inv + r0.x + b0.x;
    v0.y = acc[0].y * inv + r0.y + b0.y;
    v0.z = acc[1].x * inv + r0.z + b0.z;
    v0.w = acc[1].y * inv + r0.w + b0.w;
    v1.x = acc[2].x * inv + r1.x + b1.x;
    v1.y = acc[2].y * inv + r1.y + b1.y;
    v1.z = acc[3].x * inv + r1.z + b1.z;
    v1.w = acc[3].y * inv + r1.w + b1.w;
    o[0] = v0; o[1] = v1;
}

// ===================== fp16 mma GEMM, cp.async 2-stage, ldmatrix ==============
// DUAL:  C = A1@W1^T + A2@W2^T (+bias,+relu).  W row-major [N,K] fp16.
// !DUAL: C = A1@W1^T only. OUTHALF: fp16 C else fp32.
// CTA 128x128, BK=64 (128B rows, XOR-swizzled 16B granules), 8 warps 2x4.
#define GEMM_SMEM 65536

template <bool DUAL, bool RELU, bool OUTHALF>
__global__ void __launch_bounds__(256, 2)
gemm_h_kernel(const __half* __restrict__ A1, const __half* __restrict__ W1,
              const __half* __restrict__ A2, const __half* __restrict__ W2,
              const float* __restrict__ bias, void* __restrict__ Cout,
              int M, int N, int K) {
    extern __shared__ uint32_t sm[];
    uint32_t smb = smem_u32(sm);

    int tid = threadIdx.x, lane = tid & 31, wid = tid >> 5;
    int bm = blockIdx.x * 128, bn = blockIdx.y * 128;
    int wm = wid & 1, wn = wid >> 1;

    float acc[4][4][4];
#pragma unroll
    for (int mi = 0; mi < 4; mi++)
#pragma unroll
        for (int ni = 0; ni < 4; ni++)
#pragma unroll
            for (int r = 0; r < 4; r++) acc[mi][ni][r] = 0.0f;

    int chunks = K >> 6;                 // BK = 64 halves
    int total = DUAL ? 2 * chunks : chunks;

    auto prefetch = [&](int it, int stage) {
        int pass = DUAL ? (it >= chunks) : 0;
        int k0 = ((DUAL && pass) ? it - chunks : it) << 6;
        const __half* A = (DUAL && pass) ? A2 : A1;
        uint32_t abase = smb + stage * 32768;
        uint32_t bbase = abase + 16384;
#pragma unroll
        for (int t = 0; t < 4; t++) {
            int idx = tid + t * 256;
            int row = idx >> 3, q = idx & 7;
            uint32_t swz = (uint32_t)(q ^ (row & 7)) << 4;  // bytes
            int gr = bm + row;
            const __half* srcA = A + (size_t)(gr < M ? gr : 0) * K + k0 + q * 8;
            cp_async16(abase + row * 128 + swz, srcA, (gr < M) ? 16 : 0);
            const __half* srcB;
            if (DUAL) {
                const __half* W = pass ? W2 : W1;
                srcB = W + (size_t)(bn + row) * K + k0 + q * 8;
            } else {
                srcB = W1 + (size_t)(bn + row) * K + k0 + q * 8;
            }
            cp_async16(bbase + row * 128 + swz, srcB, 16);
        }
    };

    prefetch(0, 0);
    CP_COMMIT();

    // ldmatrix per-thread address components
    uint32_t a_row_off = (uint32_t)(wm * 64 + (lane & 15)) * 128;
    uint32_t a_gx = (uint32_t)((lane & 7) ^ ((lane >> 4) & 1));
    uint32_t b_row_off = (uint32_t)(wn * 32 + (lane & 7)) * 128;
    uint32_t b_gx = (uint32_t)((lane & 7) ^ ((lane >> 3) & 1));

    for (int it = 0; it < total; it++) {
        if (it + 1 < total) prefetch(it + 1, (it + 1) & 1);
        CP_COMMIT();
        CP_WAIT1();
        __syncthreads();

        uint32_t abase = smb + (uint32_t)(it & 1) * 32768;
        uint32_t bbase = abase + 16384;
#pragma unroll
        for (int ks = 0; ks < 4; ks++) {
            uint32_t ag = ((2u * ks) ^ a_gx) << 4;
            uint32_t bg = ((2u * ks) ^ b_gx) << 4;
            uint32_t a[4][4], b[4][2];
#pragma unroll
            for (int mi = 0; mi < 4; mi++)
                ldsm_x4(a[mi], abase + a_row_off + mi * 2048 + ag);
#pragma unroll
            for (int ni = 0; ni < 4; ni++)
                ldsm_x2(b[ni], bbase + b_row_off + ni * 1024 + bg);
#pragma unroll
            for (int mi = 0; mi < 4; mi++)
#pragma unroll
                for (int ni = 0; ni < 4; ni++)
                    mma_f16(acc[mi][ni], a[mi], b[ni]);
        }
        __syncthreads();
    }

    int qr = lane >> 2, qc2 = (lane & 3) * 2;
#pragma unroll
    for (int mi = 0; mi < 4; mi++) {
#pragma unroll
        for (int half = 0; half < 2; half++) {
            int row = bm + wm * 64 + mi * 16 + qr + half * 8;
            if (row >= M) continue;
#pragma unroll
            for (int ni = 0; ni < 4; ni++) {
                int col = bn + wn * 32 + ni * 8 + qc2;
                float ox = acc[mi][ni][half * 2 + 0];
                float oy = acc[mi][ni][half * 2 + 1];
                if (bias) { ox += bias[col]; oy += bias[col + 1]; }
                if (RELU) { ox = fmaxf(ox, 0.f); oy = fmaxf(oy, 0.f); }
                if (OUTHALF) {
                    *(uint32_t*)((__half*)Cout + (size_t)row * N + col) = pack_h2(ox, oy);
                } else {
                    *(float2*)((float*)Cout + (size_t)row * N + col) = make_float2(ox, oy);
                }
            }
        }
    }
}

// ===================== launch ==================================================
extern "C" void kernel_launch(void* const* d_in, const int* in_sizes, int n_in,
                              void* d_out, int out_size) {
    const float* x   = (const float*)d_in[0];
    const void*  ei  = d_in[1];
    const float* Wl0 = (const float*)d_in[2];
    const float* bl0 = (const float*)d_in[3];
    const float* Wr0 = (const float*)d_in[4];
    const float* Wl1 = (const float*)d_in[5];
    const float* bl1 = (const float*)d_in[6];
    const float* Wr1 = (const float*)d_in[7];
    const float* Wl2 = (const float*)d_in[8];
    const float* bl2 = (const float*)d_in[9];
    const float* Wr2 = (const float*)d_in[10];
    float*       out = (float*)d_out;

    int M = in_sizes[0] / 128;   // 50000

    __half *aggh, *h1h, *h2h, *xh, *wh, *Pl;
    float* Pr;
    cudaGetSymbolAddress((void**)&aggh, g_aggh);
    cudaGetSymbolAddress((void**)&h1h,  g_h1h);
    cudaGetSymbolAddress((void**)&h2h,  g_h2h);
    cudaGetSymbolAddress((void**)&xh,   g_xh);
    cudaGetSymbolAddress((void**)&wh,   g_wh);
    cudaGetSymbolAddress((void**)&Pl,   g_Pl);
    cudaGetSymbolAddress((void**)&Pr,   g_Pr);

    __half* wl0h = wh;
    __half* wr0h = wh + 65536;
    __half* wl1h = wh + 131072;
    __half* wr1h = wh + 393216;
    __half* wl2h = wh + 655360;
    __half* wr2h = wh + 786432;

    cudaFuncSetAttribute(gemm_h_kernel<true, true, true>,
                         cudaFuncAttributeMaxDynamicSharedMemorySize, GEMM_SMEM);
    cudaFuncSetAttribute(gemm_h_kernel<false, false, true>,
                         cudaFuncAttributeMaxDynamicSharedMemorySize, GEMM_SMEM);
    cudaFuncSetAttribute(gemm_h_kernel<false, false, false>,
                         cudaFuncAttributeMaxDynamicSharedMemorySize, GEMM_SMEM);

    // convert x + weights to fp16 (one launch)
    RoundArgs ra;
    ra.s[0] = x;   ra.d[0] = xh;   ra.n[0] = M * 128;
    ra.s[1] = Wl0; ra.d[1] = wl0h; ra.n[1] = 512 * 128;
    ra.s[2] = Wr0; ra.d[2] = wr0h; ra.n[2] = 512 * 128;
    ra.s[3] = Wl1; ra.d[3] = wl1h; ra.n[3] = 512 * 512;
    ra.s[4] = Wr1; ra.d[4] = wr1h; ra.n[4] = 512 * 512;
    ra.s[5] = Wl2; ra.d[5] = wl2h; ra.n[5] = 256 * 512;
    ra.s[6] = Wr2; ra.d[6] = wr2h; ra.n[6] = 256 * 512;
    round_all_kernel<<<dim3(256, 7), 256>>>(ra);

    // CSR build
    detect_kernel<<<1, 32>>>((const int*)ei);
    zero_counts_kernel<<<(N_NODES + 255) / 256, 256>>>();
    hist_kernel<<<(N_EDGES + 255) / 256, 256>>>(ei);
    scan1_kernel<<<50, 1024>>>();
    scan2_kernel<<<1, 64>>>();
    scan3_kernel<<<50, 1024>>>();
    scatter_kernel<<<(N_EDGES + 255) / 256, 256>>>(ei);

    int aggBlocks = (N_NODES * 32 + 255) / 256;
    int mTiles = (M + 127) / 128;

    // Layer 0: 128 -> 512, relu
    aggregate_kernel<128><<<aggBlocks, 256>>>(xh, aggh);
    gemm_h_kernel<true, true, true><<<dim3(mTiles, 4), 256, GEMM_SMEM>>>(
        aggh, wl0h, xh, wr0h, bl0, h1h, M, 512, 128);

    // Layer 1: 512 -> 512, relu
    aggregate_kernel<512><<<aggBlocks, 256>>>(h1h, aggh);
    gemm_h_kernel<true, true, true><<<dim3(mTiles, 4), 256, GEMM_SMEM>>>(
        aggh, wl1h, h1h, wr1h, bl1, h2h, M, 512, 512);

    // Layer 2 (projection-first): Pl = h2@Wl2^T (fp16), Pr = h2@Wr2^T (fp32)
    gemm_h_kernel<false, false, true><<<dim3(mTiles, 2), 256, GEMM_SMEM>>>(
        h2h, wl2h, nullptr, nullptr, nullptr, Pl, M, 256, 512);
    gemm_h_kernel<false, false, false><<<dim3(mTiles, 2), 256, GEMM_SMEM>>>(
        h2h, wr2h, nullptr, nullptr, nullptr, Pr, M, 256, 512);
    final_agg_kernel<<<aggBlocks, 256>>>(Pl, Pr, bl2, out);
}

// round 9
// speedup vs baseline: 6.6320x; 1.0369x over previous
#include <cuda_runtime.h>
#include <cuda_fp16.h>
#include <cstdint>

#define N_NODES 50000
#define N_EDGES 800000

// ===================== scratch =================================================
__device__ __half g_aggh[N_NODES * 512];
__device__ __half g_h1h[N_NODES * 512];
__device__ __half g_h2h[N_NODES * 512];
__device__ __half g_xh[N_NODES * 128];
__device__ __half g_wh[917504];
__device__ __half g_Pl[N_NODES * 256];
__device__ float  g_Pr[N_NODES * 256];
__device__ int    g_deg[N_NODES];
__device__ int    g_off[N_NODES + 1];
__device__ int    g_cur[N_NODES];
__device__ int    g_srcs[N_EDGES];
__device__ int    g_bsum[64];
__device__ int    g_boff[64];
__device__ int    g_idx64;

__device__ __forceinline__ void mma_f16(float* c, const uint32_t* a, const uint32_t* b) {
    asm volatile(
        "mma.sync.aligned.m16n8k16.row.col.f32.f16.f16.f32 "
        "{%0,%1,%2,%3}, {%4,%5,%6,%7}, {%8,%9}, {%0,%1,%2,%3};"
        : "+f"(c[0]), "+f"(c[1]), "+f"(c[2]), "+f"(c[3])
        : "r"(a[0]), "r"(a[1]), "r"(a[2]), "r"(a[3]), "r"(b[0]), "r"(b[1]));
}

__device__ __forceinline__ void ldsm_x4(uint32_t* r, uint32_t addr) {
    asm volatile("ldmatrix.sync.aligned.m8n8.x4.shared.b16 {%0,%1,%2,%3}, [%4];"
                 : "=r"(r[0]), "=r"(r[1]), "=r"(r[2]), "=r"(r[3]) : "r"(addr));
}
__device__ __forceinline__ void ldsm_x2(uint32_t* r, uint32_t addr) {
    asm volatile("ldmatrix.sync.aligned.m8n8.x2.shared.b16 {%0,%1}, [%2];"
                 : "=r"(r[0]), "=r"(r[1]) : "r"(addr));
}

__device__ __forceinline__ void cp_async16(uint32_t dst, const void* src, int sz) {
    asm volatile("cp.async.cg.shared.global [%0], [%1], 16, %2;"
                 :: "r"(dst), "l"(src), "r"(sz) : "memory");
}
#define CP_COMMIT() asm volatile("cp.async.commit_group;" ::: "memory")
#define CP_WAIT1()  asm volatile("cp.async.wait_group 1;" ::: "memory")

__device__ __forceinline__ uint32_t smem_u32(const void* p) {
    uint32_t a;
    asm("{ .reg .u64 t; cvta.to.shared.u64 t, %1; cvt.u32.u64 %0, t; }" : "=r"(a) : "l"(p));
    return a;
}

__device__ __forceinline__ void acc_u32h2(float2& a, uint32_t u) {
    __half2 h = *reinterpret_cast<__half2*>(&u);
    float2 f = __half22float2(h);
    a.x += f.x; a.y += f.y;
}
__device__ __forceinline__ uint32_t pack_h2(float x, float y) {
    __half2 h = __floats2half2_rn(x, y);
    return *reinterpret_cast<uint32_t*>(&h);
}

// ===================== fp32 -> fp16 conversion (x + weights) =================
struct RoundArgs { const float* s[7]; __half* d[7]; int n[7]; };
__global__ void round_all_kernel(RoundArgs ra) {
    int t = blockIdx.y;
    int n4 = ra.n[t] >> 2;
    const float4* s = (const float4*)ra.s[t];
    uint2* d = (uint2*)ra.d[t];
    for (int i = blockIdx.x * blockDim.x + threadIdx.x; i < n4; i += gridDim.x * blockDim.x) {
        float4 v = s[i];
        d[i] = make_uint2(pack_h2(v.x, v.y), pack_h2(v.z, v.w));
    }
}

// ===================== dtype detect (1 warp) ==================================
__global__ void detect_kernel(const int* __restrict__ ei32) {
    int lane = threadIdx.x;
    int nz = 0;
#pragma unroll
    for (int t = 0; t < 32; t++) nz |= ei32[1 + 2 * (lane + 32 * t)];
    unsigned any = __ballot_sync(0xffffffffu, nz != 0);
    if (lane == 0) g_idx64 = (any == 0u);
}

__device__ __forceinline__ int load_idx(const void* ei, long long pos) {
    if (g_idx64) return (int)((const long long*)ei)[pos];
    return ((const int*)ei)[pos];
}

// ===================== CSR build ==============================================
__global__ void zero_counts_kernel() {
    int i = blockIdx.x * blockDim.x + threadIdx.x;
    if (i < N_NODES) { g_deg[i] = 0; g_cur[i] = 0; }
}

__global__ void hist_kernel(const void* __restrict__ ei) {
    int e = blockIdx.x * blockDim.x + threadIdx.x;
    if (e < N_EDGES) {
        int d = load_idx(ei, (long long)N_EDGES + e);
        if ((unsigned)d < (unsigned)N_NODES) atomicAdd(&g_deg[d], 1);
    }
}

__global__ void scan1_kernel() {
    __shared__ int wsum[32];
    int tid = threadIdx.x, b = blockIdx.x;
    int idx = b * 1000 + tid;
    int v = (tid < 1000) ? g_deg[idx] : 0;
    int lane = tid & 31, w = tid >> 5;
    int ix = v;
#pragma unroll
    for (int o = 1; o < 32; o <<= 1) {
        int t = __shfl_up_sync(0xffffffffu, ix, o);
        if (lane >= o) ix += t;
    }
    if (lane == 31) wsum[w] = ix;
    __syncthreads();
    if (w == 0) {
        int t = wsum[lane];
#pragma unroll
        for (int o = 1; o < 32; o <<= 1) {
            int u = __shfl_up_sync(0xffffffffu, t, o);
            if (lane >= o) t += u;
        }
        wsum[lane] = t;
    }
    __syncthreads();
    int excl = ((w > 0) ? wsum[w - 1] : 0) + ix - v;
    if (tid < 1000) g_off[idx] = excl;
    if (tid == 1023) g_bsum[b] = wsum[31];
}

__global__ void scan2_kernel() {
    __shared__ int s[64];
    int tid = threadIdx.x;
    int v = (tid < 50) ? g_bsum[tid] : 0;
    s[tid] = v;
    __syncthreads();
#pragma unroll
    for (int o = 1; o < 64; o <<= 1) {
        int t = (tid >= o) ? s[tid - o] : 0;
        __syncthreads();
        s[tid] += t;
        __syncthreads();
    }
    if (tid < 50) g_boff[tid] = s[tid] - v;
    if (tid == 63) g_off[N_NODES] = s[63];
}

__global__ void scan3_kernel() {
    int tid = threadIdx.x, b = blockIdx.x;
    if (tid < 1000) g_off[b * 1000 + tid] += g_boff[b];
}

__global__ void scatter_kernel(const void* __restrict__ ei) {
    int e = blockIdx.x * blockDim.x + threadIdx.x;
    if (e < N_EDGES) {
        int s = load_idx(ei, e);
        int d = load_idx(ei, (long long)N_EDGES + e);
        if ((unsigned)d < (unsigned)N_NODES && (unsigned)s < (unsigned)N_NODES) {
            int pos = atomicAdd(&g_cur[d], 1);
            g_srcs[g_off[d] + pos] = s;
        }
    }
}

// ===================== fp16 mean aggregation (warp/node) ======================
template <int D>
__global__ void aggregate_kernel(const __half* __restrict__ feat,
                                 __half* __restrict__ out) {
    int warp = (blockIdx.x * blockDim.x + threadIdx.x) >> 5;
    if (warp >= N_NODES) return;
    int lane = threadIdx.x & 31;
    int beg = g_off[warp];
    int end = g_off[warp + 1];

    if (D == 512) {
        float2 acc[8];
#pragma unroll
        for (int j = 0; j < 8; j++) acc[j] = make_float2(0.f, 0.f);
        int i = beg;
        for (; i + 1 < end; i += 2) {
            const uint4* r0 = (const uint4*)(feat + (size_t)g_srcs[i] * 512);
            const uint4* r1 = (const uint4*)(feat + (size_t)g_srcs[i + 1] * 512);
#pragma unroll
            for (int c = 0; c < 2; c++) {
                uint4 v0 = __ldg(&r0[lane + 32 * c]);
                uint4 v1 = __ldg(&r1[lane + 32 * c]);
                acc_u32h2(acc[4 * c + 0], v0.x); acc_u32h2(acc[4 * c + 0], v1.x);
                acc_u32h2(acc[4 * c + 1], v0.y); acc_u32h2(acc[4 * c + 1], v1.y);
                acc_u32h2(acc[4 * c + 2], v0.z); acc_u32h2(acc[4 * c + 2], v1.z);
                acc_u32h2(acc[4 * c + 3], v0.w); acc_u32h2(acc[4 * c + 3], v1.w);
            }
        }
        if (i < end) {
            const uint4* r0 = (const uint4*)(feat + (size_t)g_srcs[i] * 512);
#pragma unroll
            for (int c = 0; c < 2; c++) {
                uint4 v0 = __ldg(&r0[lane + 32 * c]);
                acc_u32h2(acc[4 * c + 0], v0.x);
                acc_u32h2(acc[4 * c + 1], v0.y);
                acc_u32h2(acc[4 * c + 2], v0.z);
                acc_u32h2(acc[4 * c + 3], v0.w);
            }
        }
        int cnt = end - beg;
        float inv = 1.0f / (float)(cnt > 0 ? cnt : 1);
        uint4* o = (uint4*)(out + (size_t)warp * 512);
#pragma unroll
        for (int c = 0; c < 2; c++) {
            uint4 v;
            v.x = pack_h2(acc[4 * c + 0].x * inv, acc[4 * c + 0].y * inv);
            v.y = pack_h2(acc[4 * c + 1].x * inv, acc[4 * c + 1].y * inv);
            v.z = pack_h2(acc[4 * c + 2].x * inv, acc[4 * c + 2].y * inv);
            v.w = pack_h2(acc[4 * c + 3].x * inv, acc[4 * c + 3].y * inv);
            o[lane + 32 * c] = v;
        }
    } else {  // D == 128
        float2 acc[2];
        acc[0] = make_float2(0.f, 0.f); acc[1] = make_float2(0.f, 0.f);
        int i = beg;
        for (; i + 1 < end; i += 2) {
            uint2 v0 = __ldg((const uint2*)(feat + (size_t)g_srcs[i] * 128) + lane);
            uint2 v1 = __ldg((const uint2*)(feat + (size_t)g_srcs[i + 1] * 128) + lane);
            acc_u32h2(acc[0], v0.x); acc_u32h2(acc[0], v1.x);
            acc_u32h2(acc[1], v0.y); acc_u32h2(acc[1], v1.y);
        }
        if (i < end) {
            uint2 v0 = __ldg((const uint2*)(feat + (size_t)g_srcs[i] * 128) + lane);
            acc_u32h2(acc[0], v0.x);
            acc_u32h2(acc[1], v0.y);
        }
        int cnt = end - beg;
        float inv = 1.0f / (float)(cnt > 0 ? cnt : 1);
        uint2 v;
        v.x = pack_h2(acc[0].x * inv, acc[0].y * inv);
        v.y = pack_h2(acc[1].x * inv, acc[1].y * inv);
        *((uint2*)(out + (size_t)warp * 128) + lane) = v;
    }
}

// ===================== layer-2 final: out = mean(Pl[src]) + Pr[row] + b ========
__global__ void final_agg_kernel(const __half* __restrict__ Pl,
                                 const float* __restrict__ Pr,
                                 const float* __restrict__ bias,
                                 float* __restrict__ out) {
    int warp = (blockIdx.x * blockDim.x + threadIdx.x) >> 5;
    if (warp >= N_NODES) return;
    int lane = threadIdx.x & 31;
    int beg = g_off[warp];
    int end = g_off[warp + 1];

    float2 acc[4];
#pragma unroll
    for (int j = 0; j < 4; j++) acc[j] = make_float2(0.f, 0.f);

    int i = beg;
    for (; i + 1 < end; i += 2) {
        uint4 v0 = __ldg((const uint4*)(Pl + (size_t)g_srcs[i] * 256) + lane);
        uint4 v1 = __ldg((const uint4*)(Pl + (size_t)g_srcs[i + 1] * 256) + lane);
        acc_u32h2(acc[0], v0.x); acc_u32h2(acc[0], v1.x);
        acc_u32h2(acc[1], v0.y); acc_u32h2(acc[1], v1.y);
        acc_u32h2(acc[2], v0.z); acc_u32h2(acc[2], v1.z);
        acc_u32h2(acc[3], v0.w); acc_u32h2(acc[3], v1.w);
    }
    if (i < end) {
        uint4 v0 = __ldg((const uint4*)(Pl + (size_t)g_srcs[i] * 256) + lane);
        acc_u32h2(acc[0], v0.x);
        acc_u32h2(acc[1], v0.y);
        acc_u32h2(acc[2], v0.z);
        acc_u32h2(acc[3], v0.w);
    }
    int cnt = end - beg;
    float inv = 1.0f / (float)(cnt > 0 ? cnt : 1);
    const float4* pr = (const float4*)(Pr + (size_t)warp * 256 + lane * 8);
    const float4* bb = (const float4*)(bias + lane * 8);
    float4* o = (float4*)(out + (size_t)warp * 256 + lane * 8);
    float4 r0 = __ldg(&pr[0]), r1 = __ldg(&pr[1]);
    float4 b0 = bb[0], b1 = bb[1];
    float4 v0, v1;
    v0.x = acc[0].x * inv + r0.x + b0.x;
    v0.y = acc[0].y * inv + r0.y + b0.y;
    v0.z = acc[1].x * inv + r0.z + b0.z;
    v0.w = acc[1].y * inv + r0.w + b0.w;
    v1.x = acc[2].x * inv + r1.x + b1.x;
    v1.y = acc[2].y * inv + r1.y + b1.y;
    v1.z = acc[3].x * inv + r1.z + b1.z;
    v1.w = acc[3].y * inv + r1.w + b1.w;
    o[0] = v0; o[1] = v1;
}

// ===================== fp16 mma GEMM, cp.async 3-stage, ldmatrix ==============
// DUAL:   C = A1@W1^T + A2@W2^T (+bias,+relu), fp16 out.
// SPLIT:  C = A1@W1^T; cols < Nsplit -> fp16 Cout (stride Nsplit),
//                       cols >= Nsplit -> fp32 Cout2 (stride N-Nsplit).
// CTA 128x128, BK=64 (128B rows, XOR-swizzled 16B granules), 8 warps 2x4.
// 3 stages x 32KB = 96KB smem; ONE __syncthreads per iteration.
#define GEMM_SMEM 98304

template <bool DUAL, bool RELU, bool SPLIT>
__global__ void __launch_bounds__(256, 2)
gemm_h_kernel(const __half* __restrict__ A1, const __half* __restrict__ W1,
              const __half* __restrict__ A2, const __half* __restrict__ W2,
              const float* __restrict__ bias, void* __restrict__ Cout,
              float* __restrict__ Cout2, int M, int N, int K, int Nsplit) {
    extern __shared__ uint32_t sm[];
    uint32_t smb = smem_u32(sm);

    int tid = threadIdx.x, lane = tid & 31, wid = tid >> 5;
    int bm = blockIdx.x * 128, bn = blockIdx.y * 128;
    int wm = wid & 1, wn = wid >> 1;

    float acc[4][4][4];
#pragma unroll
    for (int mi = 0; mi < 4; mi++)
#pragma unroll
        for (int ni = 0; ni < 4; ni++)
#pragma unroll
            for (int r = 0; r < 4; r++) acc[mi][ni][r] = 0.0f;

    int chunks = K >> 6;                 // BK = 64 halves
    int total = DUAL ? 2 * chunks : chunks;

    auto prefetch = [&](int it, int stage) {
        int pass = DUAL ? (it >= chunks) : 0;
        int k0 = ((DUAL && pass) ? it - chunks : it) << 6;
        const __half* A = (DUAL && pass) ? A2 : A1;
        const __half* W = (DUAL && pass) ? W2 : W1;
        uint32_t abase = smb + stage * 32768;
        uint32_t bbase = abase + 16384;
#pragma unroll
        for (int t = 0; t < 4; t++) {
            int idx = tid + t * 256;
            int row = idx >> 3, q = idx & 7;
            uint32_t swz = (uint32_t)(q ^ (row & 7)) << 4;  // bytes
            int gr = bm + row;
            const __half* srcA = A + (size_t)(gr < M ? gr : 0) * K + k0 + q * 8;
            cp_async16(abase + row * 128 + swz, srcA, (gr < M) ? 16 : 0);
            const __half* srcB = W + (size_t)(bn + row) * K + k0 + q * 8;
            cp_async16(bbase + row * 128 + swz, srcB, 16);
        }
    };

    prefetch(0, 0); CP_COMMIT();
    prefetch(1, 1); CP_COMMIT();

    // ldmatrix per-thread address components
    uint32_t a_row_off = (uint32_t)(wm * 64 + (lane & 15)) * 128;
    uint32_t a_gx = (uint32_t)((lane & 7) ^ ((lane >> 4) & 1));
    uint32_t b_row_off = (uint32_t)(wn * 32 + (lane & 7)) * 128;
    uint32_t b_gx = (uint32_t)((lane & 7) ^ ((lane >> 3) & 1));

    int stage = 0;
    for (int it = 0; it < total; it++) {
        CP_WAIT1();
        __syncthreads();
        // prefetch 2 ahead into the buffer consumed at it-1 (readers are past barrier)
        if (it + 2 < total) {
            int ps = stage + 2; if (ps >= 3) ps -= 3;
            prefetch(it + 2, ps);
        }
        CP_COMMIT();

        uint32_t abase = smb + (uint32_t)stage * 32768;
        uint32_t bbase = abase + 16384;
#pragma unroll
        for (int ks = 0; ks < 4; ks++) {
            uint32_t ag = ((2u * ks) ^ a_gx) << 4;
            uint32_t bg = ((2u * ks) ^ b_gx) << 4;
            uint32_t a[4][4], b[4][2];
#pragma unroll
            for (int mi = 0; mi < 4; mi++)
                ldsm_x4(a[mi], abase + a_row_off + mi * 2048 + ag);
#pragma unroll
            for (int ni = 0; ni < 4; ni++)
                ldsm_x2(b[ni], bbase + b_row_off + ni * 1024 + bg);
#pragma unroll
            for (int mi = 0; mi < 4; mi++)
#pragma unroll
                for (int ni = 0; ni < 4; ni++)
                    mma_f16(acc[mi][ni], a[mi], b[ni]);
        }
        if (++stage == 3) stage = 0;
    }

    int qr = lane >> 2, qc2 = (lane & 3) * 2;
#pragma unroll
    for (int mi = 0; mi < 4; mi++) {
#pragma unroll
        for (int half = 0; half < 2; half++) {
            int row = bm + wm * 64 + mi * 16 + qr + half * 8;
            if (row >= M) continue;
#pragma unroll
            for (int ni = 0; ni < 4; ni++) {
                int col = bn + wn * 32 + ni * 8 + qc2;
                float ox = acc[mi][ni][half * 2 + 0];
                float oy = acc[mi][ni][half * 2 + 1];
                if (SPLIT) {
                    if (col < Nsplit) {
                        *(uint32_t*)((__half*)Cout + (size_t)row * Nsplit + col) = pack_h2(ox, oy);
                    } else {
                        *(float2*)(Cout2 + (size_t)row * (N - Nsplit) + (col - Nsplit)) =
                            make_float2(ox, oy);
                    }
                } else {
                    ox += bias[col]; oy += bias[col + 1];
                    if (RELU) { ox = fmaxf(ox, 0.f); oy = fmaxf(oy, 0.f); }
                    *(uint32_t*)((__half*)Cout + (size_t)row * N + col) = pack_h2(ox, oy);
                }
            }
        }
    }
}

// ===================== launch ==================================================
extern "C" void kernel_launch(void* const* d_in, const int* in_sizes, int n_in,
                              void* d_out, int out_size) {
    const float* x   = (const float*)d_in[0];
    const void*  ei  = d_in[1];
    const float* Wl0 = (const float*)d_in[2];
    const float* bl0 = (const float*)d_in[3];
    const float* Wr0 = (const float*)d_in[4];
    const float* Wl1 = (const float*)d_in[5];
    const float* bl1 = (const float*)d_in[6];
    const float* Wr1 = (const float*)d_in[7];
    const float* Wl2 = (const float*)d_in[8];
    const float* bl2 = (const float*)d_in[9];
    const float* Wr2 = (const float*)d_in[10];
    float*       out = (float*)d_out;

    int M = in_sizes[0] / 128;   // 50000

    __half *aggh, *h1h, *h2h, *xh, *wh, *Pl;
    float* Pr;
    cudaGetSymbolAddress((void**)&aggh, g_aggh);
    cudaGetSymbolAddress((void**)&h1h,  g_h1h);
    cudaGetSymbolAddress((void**)&h2h,  g_h2h);
    cudaGetSymbolAddress((void**)&xh,   g_xh);
    cudaGetSymbolAddress((void**)&wh,   g_wh);
    cudaGetSymbolAddress((void**)&Pl,   g_Pl);
    cudaGetSymbolAddress((void**)&Pr,   g_Pr);

    __half* wl0h = wh;
    __half* wr0h = wh + 65536;
    __half* wl1h = wh + 131072;
    __half* wr1h = wh + 393216;
    __half* wl2h = wh + 655360;   // [Wl2;Wr2] contiguous = one [512,512] matrix
    __half* wr2h = wh + 786432;

    cudaFuncSetAttribute(gemm_h_kernel<true, true, false>,
                         cudaFuncAttributeMaxDynamicSharedMemorySize, GEMM_SMEM);
    cudaFuncSetAttribute(gemm_h_kernel<false, false, true>,
                         cudaFuncAttributeMaxDynamicSharedMemorySize, GEMM_SMEM);

    // convert x + weights to fp16 (one launch)
    RoundArgs ra;
    ra.s[0] = x;   ra.d[0] = xh;   ra.n[0] = M * 128;
    ra.s[1] = Wl0; ra.d[1] = wl0h; ra.n[1] = 512 * 128;
    ra.s[2] = Wr0; ra.d[2] = wr0h; ra.n[2] = 512 * 128;
    ra.s[3] = Wl1; ra.d[3] = wl1h; ra.n[3] = 512 * 512;
    ra.s[4] = Wr1; ra.d[4] = wr1h; ra.n[4] = 512 * 512;
    ra.s[5] = Wl2; ra.d[5] = wl2h; ra.n[5] = 256 * 512;
    ra.s[6] = Wr2; ra.d[6] = wr2h; ra.n[6] = 256 * 512;
    round_all_kernel<<<dim3(256, 7), 256>>>(ra);

    // CSR build
    detect_kernel<<<1, 32>>>((const int*)ei);
    zero_counts_kernel<<<(N_NODES + 255) / 256, 256>>>();
    hist_kernel<<<(N_EDGES + 255) / 256, 256>>>(ei);
    scan1_kernel<<<50, 1024>>>();
    scan2_kernel<<<1, 64>>>();
    scan3_kernel<<<50, 1024>>>();
    scatter_kernel<<<(N_EDGES + 255) / 256, 256>>>(ei);

    int aggBlocks = (N_NODES * 32 + 255) / 256;
    int mTiles = (M + 127) / 128;

    // Layer 0: 128 -> 512, relu
    aggregate_kernel<128><<<aggBlocks, 256>>>(xh, aggh);
    gemm_h_kernel<true, true, false><<<dim3(mTiles, 4), 256, GEMM_SMEM>>>(
        aggh, wl0h, xh, wr0h, bl0, h1h, nullptr, M, 512, 128, 0);

    // Layer 1: 512 -> 512, relu
    aggregate_kernel<512><<<aggBlocks, 256>>>(h1h, aggh);
    gemm_h_kernel<true, true, false><<<dim3(mTiles, 4), 256, GEMM_SMEM>>>(
        aggh, wl1h, h1h, wr1h, bl1, h2h, nullptr, M, 512, 512, 0);

    // Layer 2 (projection-first, single GEMM over [Wl2;Wr2]):
    //   cols 0-255 -> Pl fp16, cols 256-511 -> Pr fp32
    gemm_h_kernel<false, false, true><<<dim3(mTiles, 4), 256, GEMM_SMEM>>>(
        h2h, wl2h, nullptr, nullptr, nullptr, Pl, Pr, M, 512, 512, 256);
    final_agg_kernel<<<aggBlocks, 256>>>(Pl, Pr, bl2, out);
}

// round 10
// speedup vs baseline: 6.9475x; 1.0476x over previous
#include <cuda_runtime.h>
#include <cuda_fp16.h>
#include <cstdint>

#define N_NODES 50000
#define N_EDGES 800000

// ===================== scratch =================================================
__device__ __half g_aggh[N_NODES * 512];
__device__ __half g_h1h[N_NODES * 512];
__device__ __half g_h2h[N_NODES * 512];
__device__ __half g_xh[N_NODES * 128];
__device__ __half g_wh[917504];
__device__ __half g_Pl[N_NODES * 256];
__device__ float  g_Pr[N_NODES * 256];
__device__ int    g_deg[N_NODES];
__device__ int    g_off[N_NODES + 1];
__device__ int    g_cur[N_NODES];
__device__ int    g_srcs[N_EDGES];
__device__ int    g_bsum[64];
__device__ int    g_boff[64];
__device__ int    g_idx64;

__device__ __forceinline__ void mma_f16(float* c, const uint32_t* a, const uint32_t* b) {
    asm volatile(
        "mma.sync.aligned.m16n8k16.row.col.f32.f16.f16.f32 "
        "{%0,%1,%2,%3}, {%4,%5,%6,%7}, {%8,%9}, {%0,%1,%2,%3};"
        : "+f"(c[0]), "+f"(c[1]), "+f"(c[2]), "+f"(c[3])
        : "r"(a[0]), "r"(a[1]), "r"(a[2]), "r"(a[3]), "r"(b[0]), "r"(b[1]));
}

__device__ __forceinline__ void ldsm_x4(uint32_t* r, uint32_t addr) {
    asm volatile("ldmatrix.sync.aligned.m8n8.x4.shared.b16 {%0,%1,%2,%3}, [%4];"
                 : "=r"(r[0]), "=r"(r[1]), "=r"(r[2]), "=r"(r[3]) : "r"(addr));
}
__device__ __forceinline__ void ldsm_x2(uint32_t* r, uint32_t addr) {
    asm volatile("ldmatrix.sync.aligned.m8n8.x2.shared.b16 {%0,%1}, [%2];"
                 : "=r"(r[0]), "=r"(r[1]) : "r"(addr));
}

__device__ __forceinline__ void cp_async16(uint32_t dst, const void* src, int sz) {
    asm volatile("cp.async.cg.shared.global [%0], [%1], 16, %2;"
                 :: "r"(dst), "l"(src), "r"(sz) : "memory");
}
#define CP_COMMIT() asm volatile("cp.async.commit_group;" ::: "memory")
#define CP_WAIT1()  asm volatile("cp.async.wait_group 1;" ::: "memory")

__device__ __forceinline__ uint32_t smem_u32(const void* p) {
    uint32_t a;
    asm("{ .reg .u64 t; cvta.to.shared.u64 t, %1; cvt.u32.u64 %0, t; }" : "=r"(a) : "l"(p));
    return a;
}

__device__ __forceinline__ void acc_u32h2(float2& a, uint32_t u) {
    __half2 h = *reinterpret_cast<__half2*>(&u);
    float2 f = __half22float2(h);
    a.x += f.x; a.y += f.y;
}
__device__ __forceinline__ uint32_t pack_h2(float x, float y) {
    __half2 h = __floats2half2_rn(x, y);
    return *reinterpret_cast<uint32_t*>(&h);
}

// ===================== fp32 -> fp16 conversion (x + weights) =================
struct RoundArgs { const float* s[7]; __half* d[7]; int n[7]; };
__global__ void round_all_kernel(RoundArgs ra) {
    int t = blockIdx.y;
    int n4 = ra.n[t] >> 2;
    const float4* s = (const float4*)ra.s[t];
    uint2* d = (uint2*)ra.d[t];
    for (int i = blockIdx.x * blockDim.x + threadIdx.x; i < n4; i += gridDim.x * blockDim.x) {
        float4 v = s[i];
        d[i] = make_uint2(pack_h2(v.x, v.y), pack_h2(v.z, v.w));
    }
}

// ===================== CSR build ==============================================
// zero + dtype detect fused (block 0 warp 0 probes int64-vs-int32)
__global__ void zero_detect_kernel(const int* __restrict__ ei32) {
    int i = blockIdx.x * blockDim.x + threadIdx.x;
    if (i < N_NODES) { g_deg[i] = 0; g_cur[i] = 0; }
    if (blockIdx.x == 0 && threadIdx.x < 32) {
        int lane = threadIdx.x;
        int nz = 0;
#pragma unroll
        for (int t = 0; t < 32; t++) nz |= ei32[1 + 2 * (lane + 32 * t)];
        unsigned any = __ballot_sync(0xffffffffu, nz != 0);
        if (lane == 0) g_idx64 = (any == 0u);
    }
}

__device__ __forceinline__ int load_idx(const void* ei, long long pos) {
    if (g_idx64) return (int)((const long long*)ei)[pos];
    return ((const int*)ei)[pos];
}

__global__ void hist_kernel(const void* __restrict__ ei) {
    int e = blockIdx.x * blockDim.x + threadIdx.x;
    if (e < N_EDGES) {
        int d = load_idx(ei, (long long)N_EDGES + e);
        if ((unsigned)d < (unsigned)N_NODES) atomicAdd(&g_deg[d], 1);
    }
}

__global__ void scan1_kernel() {
    __shared__ int wsum[32];
    int tid = threadIdx.x, b = blockIdx.x;
    int idx = b * 1000 + tid;
    int v = (tid < 1000) ? g_deg[idx] : 0;
    int lane = tid & 31, w = tid >> 5;
    int ix = v;
#pragma unroll
    for (int o = 1; o < 32; o <<= 1) {
        int t = __shfl_up_sync(0xffffffffu, ix, o);
        if (lane >= o) ix += t;
    }
    if (lane == 31) wsum[w] = ix;
    __syncthreads();
    if (w == 0) {
        int t = wsum[lane];
#pragma unroll
        for (int o = 1; o < 32; o <<= 1) {
            int u = __shfl_up_sync(0xffffffffu, t, o);
            if (lane >= o) t += u;
        }
        wsum[lane] = t;
    }
    __syncthreads();
    int excl = ((w > 0) ? wsum[w - 1] : 0) + ix - v;
    if (tid < 1000) g_off[idx] = excl;
    if (tid == 1023) g_bsum[b] = wsum[31];
}

__global__ void scan2_kernel() {
    __shared__ int s[64];
    int tid = threadIdx.x;
    int v = (tid < 50) ? g_bsum[tid] : 0;
    s[tid] = v;
    __syncthreads();
#pragma unroll
    for (int o = 1; o < 64; o <<= 1) {
        int t = (tid >= o) ? s[tid - o] : 0;
        __syncthreads();
        s[tid] += t;
        __syncthreads();
    }
    if (tid < 50) g_boff[tid] = s[tid] - v;
    if (tid == 63) g_off[N_NODES] = s[63];
}

__global__ void scan3_kernel() {
    int tid = threadIdx.x, b = blockIdx.x;
    if (tid < 1000) g_off[b * 1000 + tid] += g_boff[b];
}

__global__ void scatter_kernel(const void* __restrict__ ei) {
    int e = blockIdx.x * blockDim.x + threadIdx.x;
    if (e < N_EDGES) {
        int s = load_idx(ei, e);
        int d = load_idx(ei, (long long)N_EDGES + e);
        if ((unsigned)d < (unsigned)N_NODES && (unsigned)s < (unsigned)N_NODES) {
            int pos = atomicAdd(&g_cur[d], 1);
            g_srcs[g_off[d] + pos] = s;
        }
    }
}

// ===================== fp16 mean aggregation (warp/node, unroll-4) ============
template <int D>
__global__ void aggregate_kernel(const __half* __restrict__ feat,
                                 __half* __restrict__ out) {
    int warp = (blockIdx.x * blockDim.x + threadIdx.x) >> 5;
    if (warp >= N_NODES) return;
    int lane = threadIdx.x & 31;
    int beg = g_off[warp];
    int end = g_off[warp + 1];

    if (D == 512) {
        float2 acc[8];
#pragma unroll
        for (int j = 0; j < 8; j++) acc[j] = make_float2(0.f, 0.f);
        int i = beg;
        for (; i + 3 < end; i += 4) {
            const uint4* p0 = (const uint4*)(feat + (size_t)g_srcs[i] * 512);
            const uint4* p1 = (const uint4*)(feat + (size_t)g_srcs[i + 1] * 512);
            const uint4* p2 = (const uint4*)(feat + (size_t)g_srcs[i + 2] * 512);
            const uint4* p3 = (const uint4*)(feat + (size_t)g_srcs[i + 3] * 512);
#pragma unroll
            for (int c = 0; c < 2; c++) {
                uint4 v0 = __ldg(&p0[lane + 32 * c]);
                uint4 v1 = __ldg(&p1[lane + 32 * c]);
                uint4 v2 = __ldg(&p2[lane + 32 * c]);
                uint4 v3 = __ldg(&p3[lane + 32 * c]);
                acc_u32h2(acc[4 * c + 0], v0.x); acc_u32h2(acc[4 * c + 0], v1.x);
                acc_u32h2(acc[4 * c + 0], v2.x); acc_u32h2(acc[4 * c + 0], v3.x);
                acc_u32h2(acc[4 * c + 1], v0.y); acc_u32h2(acc[4 * c + 1], v1.y);
                acc_u32h2(acc[4 * c + 1], v2.y); acc_u32h2(acc[4 * c + 1], v3.y);
                acc_u32h2(acc[4 * c + 2], v0.z); acc_u32h2(acc[4 * c + 2], v1.z);
                acc_u32h2(acc[4 * c + 2], v2.z); acc_u32h2(acc[4 * c + 2], v3.z);
                acc_u32h2(acc[4 * c + 3], v0.w); acc_u32h2(acc[4 * c + 3], v1.w);
                acc_u32h2(acc[4 * c + 3], v2.w); acc_u32h2(acc[4 * c + 3], v3.w);
            }
        }
        for (; i < end; i++) {
            const uint4* p0 = (const uint4*)(feat + (size_t)g_srcs[i] * 512);
#pragma unroll
            for (int c = 0; c < 2; c++) {
                uint4 v0 = __ldg(&p0[lane + 32 * c]);
                acc_u32h2(acc[4 * c + 0], v0.x);
                acc_u32h2(acc[4 * c + 1], v0.y);
                acc_u32h2(acc[4 * c + 2], v0.z);
                acc_u32h2(acc[4 * c + 3], v0.w);
            }
        }
        int cnt = end - beg;
        float inv = 1.0f / (float)(cnt > 0 ? cnt : 1);
        uint4* o = (uint4*)(out + (size_t)warp * 512);
#pragma unroll
        for (int c = 0; c < 2; c++) {
            uint4 v;
            v.x = pack_h2(acc[4 * c + 0].x * inv, acc[4 * c + 0].y * inv);
            v.y = pack_h2(acc[4 * c + 1].x * inv, acc[4 * c + 1].y * inv);
            v.z = pack_h2(acc[4 * c + 2].x * inv, acc[4 * c + 2].y * inv);
            v.w = pack_h2(acc[4 * c + 3].x * inv, acc[4 * c + 3].y * inv);
            o[lane + 32 * c] = v;
        }
    } else {  // D == 128
        float2 acc[2];
        acc[0] = make_float2(0.f, 0.f); acc[1] = make_float2(0.f, 0.f);
        int i = beg;
        for (; i + 3 < end; i += 4) {
            uint2 v0 = __ldg((const uint2*)(feat + (size_t)g_srcs[i] * 128) + lane);
            uint2 v1 = __ldg((const uint2*)(feat + (size_t)g_srcs[i + 1] * 128) + lane);
            uint2 v2 = __ldg((const uint2*)(feat + (size_t)g_srcs[i + 2] * 128) + lane);
            uint2 v3 = __ldg((const uint2*)(feat + (size_t)g_srcs[i + 3] * 128) + lane);
            acc_u32h2(acc[0], v0.x); acc_u32h2(acc[0], v1.x);
            acc_u32h2(acc[0], v2.x); acc_u32h2(acc[0], v3.x);
            acc_u32h2(acc[1], v0.y); acc_u32h2(acc[1], v1.y);
            acc_u32h2(acc[1], v2.y); acc_u32h2(acc[1], v3.y);
        }
        for (; i < end; i++) {
            uint2 v0 = __ldg((const uint2*)(feat + (size_t)g_srcs[i] * 128) + lane);
            acc_u32h2(acc[0], v0.x);
            acc_u32h2(acc[1], v0.y);
        }
        int cnt = end - beg;
        float inv = 1.0f / (float)(cnt > 0 ? cnt : 1);
        uint2 v;
        v.x = pack_h2(acc[0].x * inv, acc[0].y * inv);
        v.y = pack_h2(acc[1].x * inv, acc[1].y * inv);
        *((uint2*)(out + (size_t)warp * 128) + lane) = v;
    }
}

// ===================== layer-2 final: out = mean(Pl[src]) + Pr[row] + b ========
__global__ void final_agg_kernel(const __half* __restrict__ Pl,
                                 const float* __restrict__ Pr,
                                 const float* __restrict__ bias,
                                 float* __restrict__ out) {
    int warp = (blockIdx.x * blockDim.x + threadIdx.x) >> 5;
    if (warp >= N_NODES) return;
    int lane = threadIdx.x & 31;
    int beg = g_off[warp];
    int end = g_off[warp + 1];

    float2 acc[4];
#pragma unroll
    for (int j = 0; j < 4; j++) acc[j] = make_float2(0.f, 0.f);

    int i = beg;
    for (; i + 3 < end; i += 4) {
        uint4 v0 = __ldg((const uint4*)(Pl + (size_t)g_srcs[i] * 256) + lane);
        uint4 v1 = __ldg((const uint4*)(Pl + (size_t)g_srcs[i + 1] * 256) + lane);
        uint4 v2 = __ldg((const uint4*)(Pl + (size_t)g_srcs[i + 2] * 256) + lane);
        uint4 v3 = __ldg((const uint4*)(Pl + (size_t)g_srcs[i + 3] * 256) + lane);
        acc_u32h2(acc[0], v0.x); acc_u32h2(acc[0], v1.x);
        acc_u32h2(acc[0], v2.x); acc_u32h2(acc[0], v3.x);
        acc_u32h2(acc[1], v0.y); acc_u32h2(acc[1], v1.y);
        acc_u32h2(acc[1], v2.y); acc_u32h2(acc[1], v3.y);
        acc_u32h2(acc[2], v0.z); acc_u32h2(acc[2], v1.z);
        acc_u32h2(acc[2], v2.z); acc_u32h2(acc[2], v3.z);
        acc_u32h2(acc[3], v0.w); acc_u32h2(acc[3], v1.w);
        acc_u32h2(acc[3], v2.w); acc_u32h2(acc[3], v3.w);
    }
    for (; i < end; i++) {
        uint4 v0 = __ldg((const uint4*)(Pl + (size_t)g_srcs[i] * 256) + lane);
        acc_u32h2(acc[0], v0.x);
        acc_u32h2(acc[1], v0.y);
        acc_u32h2(acc[2], v0.z);
        acc_u32h2(acc[3], v0.w);
    }
    int cnt = end - beg;
    float inv = 1.0f / (float)(cnt > 0 ? cnt : 1);
    const float4* pr = (const float4*)(Pr + (size_t)warp * 256 + lane * 8);
    const float4* bb = (const float4*)(bias + lane * 8);
    float4* o = (float4*)(out + (size_t)warp * 256 + lane * 8);
    float4 r0 = __ldg(&pr[0]), r1 = __ldg(&pr[1]);
    float4 b0 = bb[0], b1 = bb[1];
    float4 v0, v1;
    v0.x = acc[0].x * inv + r0.x + b0.x;
    v0.y = acc[0].y * inv + r0.y + b0.y;
    v0.z = acc[1].x * inv + r0.z + b0.z;
    v0.w = acc[1].y * inv + r0.w + b0.w;
    v1.x = acc[2].x * inv + r1.x + b1.x;
    v1.y = acc[2].y * inv + r1.y + b1.y;
    v1.z = acc[3].x * inv + r1.z + b1.z;
    v1.w = acc[3].y * inv + r1.w + b1.w;
    o[0] = v0; o[1] = v1;
}

// ===================== fp16 mma GEMM, cp.async 3-stage, ldmatrix ==============
#define GEMM_SMEM 98304

template <bool DUAL, bool RELU, bool SPLIT>
__global__ void __launch_bounds__(256, 2)
gemm_h_kernel(const __half* __restrict__ A1, const __half* __restrict__ W1,
              const __half* __restrict__ A2, const __half* __restrict__ W2,
              const float* __restrict__ bias, void* __restrict__ Cout,
              float* __restrict__ Cout2, int M, int N, int K, int Nsplit) {
    extern __shared__ uint32_t sm[];
    uint32_t smb = smem_u32(sm);

    int tid = threadIdx.x, lane = tid & 31, wid = tid >> 5;
    int bm = blockIdx.x * 128, bn = blockIdx.y * 128;
    int wm = wid & 1, wn = wid >> 1;

    float acc[4][4][4];
#pragma unroll
    for (int mi = 0; mi < 4; mi++)
#pragma unroll
        for (int ni = 0; ni < 4; ni++)
#pragma unroll
            for (int r = 0; r < 4; r++) acc[mi][ni][r] = 0.0f;

    int chunks = K >> 6;                 // BK = 64 halves
    int total = DUAL ? 2 * chunks : chunks;

    auto prefetch = [&](int it, int stage) {
        int pass = DUAL ? (it >= chunks) : 0;
        int k0 = ((DUAL && pass) ? it - chunks : it) << 6;
        const __half* A = (DUAL && pass) ? A2 : A1;
        const __half* W = (DUAL && pass) ? W2 : W1;
        uint32_t abase = smb + stage * 32768;
        uint32_t bbase = abase + 16384;
#pragma unroll
        for (int t = 0; t < 4; t++) {
            int idx = tid + t * 256;
            int row = idx >> 3, q = idx & 7;
            uint32_t swz = (uint32_t)(q ^ (row & 7)) << 4;  // bytes
            int gr = bm + row;
            const __half* srcA = A + (size_t)(gr < M ? gr : 0) * K + k0 + q * 8;
            cp_async16(abase + row * 128 + swz, srcA, (gr < M) ? 16 : 0);
            const __half* srcB = W + (size_t)(bn + row) * K + k0 + q * 8;
            cp_async16(bbase + row * 128 + swz, srcB, 16);
        }
    };

    prefetch(0, 0); CP_COMMIT();
    prefetch(1, 1); CP_COMMIT();

    uint32_t a_row_off = (uint32_t)(wm * 64 + (lane & 15)) * 128;
    uint32_t a_gx = (uint32_t)((lane & 7) ^ ((lane >> 4) & 1));
    uint32_t b_row_off = (uint32_t)(wn * 32 + (lane & 7)) * 128;
    uint32_t b_gx = (uint32_t)((lane & 7) ^ ((lane >> 3) & 1));

    int stage = 0;
    for (int it = 0; it < total; it++) {
        CP_WAIT1();
        __syncthreads();
        if (it + 2 < total) {
            int ps = stage + 2; if (ps >= 3) ps -= 3;
            prefetch(it + 2, ps);
        }
        CP_COMMIT();

        uint32_t abase = smb + (uint32_t)stage * 32768;
        uint32_t bbase = abase + 16384;
#pragma unroll
        for (int ks = 0; ks < 4; ks++) {
            uint32_t ag = ((2u * ks) ^ a_gx) << 4;
            uint32_t bg = ((2u * ks) ^ b_gx) << 4;
            uint32_t a[4][4], b[4][2];
#pragma unroll
            for (int mi = 0; mi < 4; mi++)
                ldsm_x4(a[mi], abase + a_row_off + mi * 2048 + ag);
#pragma unroll
            for (int ni = 0; ni < 4; ni++)
                ldsm_x2(b[ni], bbase + b_row_off + ni * 1024 + bg);
#pragma unroll
            for (int mi = 0; mi < 4; mi++)
#pragma unroll
                for (int ni = 0; ni < 4; ni++)
                    mma_f16(acc[mi][ni], a[mi], b[ni]);
        }
        if (++stage == 3) stage = 0;
    }

    int qr = lane >> 2, qc2 = (lane & 3) * 2;
#pragma unroll
    for (int mi = 0; mi < 4; mi++) {
#pragma unroll
        for (int half = 0; half < 2; half++) {
            int row = bm + wm * 64 + mi * 16 + qr + half * 8;
            if (row >= M) continue;
#pragma unroll
            for (int ni = 0; ni < 4; ni++) {
                int col = bn + wn * 32 + ni * 8 + qc2;
                float ox = acc[mi][ni][half * 2 + 0];
                float oy = acc[mi][ni][half * 2 + 1];
                if (SPLIT) {
                    if (col < Nsplit) {
                        *(uint32_t*)((__half*)Cout + (size_t)row * Nsplit + col) = pack_h2(ox, oy);
                    } else {
                        *(float2*)(Cout2 + (size_t)row * (N - Nsplit) + (col - Nsplit)) =
                            make_float2(ox, oy);
                    }
                } else {
                    ox += bias[col]; oy += bias[col + 1];
                    if (RELU) { ox = fmaxf(ox, 0.f); oy = fmaxf(oy, 0.f); }
                    *(uint32_t*)((__half*)Cout + (size_t)row * N + col) = pack_h2(ox, oy);
                }
            }
        }
    }
}

// ===================== launch ==================================================
extern "C" void kernel_launch(void* const* d_in, const int* in_sizes, int n_in,
                              void* d_out, int out_size) {
    const float* x   = (const float*)d_in[0];
    const void*  ei  = d_in[1];
    const float* Wl0 = (const float*)d_in[2];
    const float* bl0 = (const float*)d_in[3];
    const float* Wr0 = (const float*)d_in[4];
    const float* Wl1 = (const float*)d_in[5];
    const float* bl1 = (const float*)d_in[6];
    const float* Wr1 = (const float*)d_in[7];
    const float* Wl2 = (const float*)d_in[8];
    const float* bl2 = (const float*)d_in[9];
    const float* Wr2 = (const float*)d_in[10];
    float*       out = (float*)d_out;

    int M = in_sizes[0] / 128;   // 50000

    __half *aggh, *h1h, *h2h, *xh, *wh, *Pl;
    float* Pr;
    cudaGetSymbolAddress((void**)&aggh, g_aggh);
    cudaGetSymbolAddress((void**)&h1h,  g_h1h);
    cudaGetSymbolAddress((void**)&h2h,  g_h2h);
    cudaGetSymbolAddress((void**)&xh,   g_xh);
    cudaGetSymbolAddress((void**)&wh,   g_wh);
    cudaGetSymbolAddress((void**)&Pl,   g_Pl);
    cudaGetSymbolAddress((void**)&Pr,   g_Pr);

    __half* wl0h = wh;
    __half* wr0h = wh + 65536;
    __half* wl1h = wh + 131072;
    __half* wr1h = wh + 393216;
    __half* wl2h = wh + 655360;   // [Wl2;Wr2] contiguous = one [512,512] matrix
    __half* wr2h = wh + 786432;

    cudaFuncSetAttribute(gemm_h_kernel<true, true, false>,
                         cudaFuncAttributeMaxDynamicSharedMemorySize, GEMM_SMEM);
    cudaFuncSetAttribute(gemm_h_kernel<false, false, true>,
                         cudaFuncAttributeMaxDynamicSharedMemorySize, GEMM_SMEM);

    // lazily-created side stream + fork/join events (host-side resources only;
    // no device memory allocation). Work is identical every call.
    static cudaStream_t s2 = nullptr;
    static cudaEvent_t  eFork = nullptr, eJoin = nullptr;
    if (!s2) {
        cudaStreamCreateWithFlags(&s2, cudaStreamNonBlocking);
        cudaEventCreateWithFlags(&eFork, cudaEventDisableTiming);
        cudaEventCreateWithFlags(&eJoin, cudaEventDisableTiming);
    }

    // ---- fork: fp16 conversion runs on s2, CSR build on the main stream ----
    cudaEventRecord(eFork, 0);
    cudaStreamWaitEvent(s2, eFork, 0);

    RoundArgs ra;
    ra.s[0] = x;   ra.d[0] = xh;   ra.n[0] = M * 128;
    ra.s[1] = Wl0; ra.d[1] = wl0h; ra.n[1] = 512 * 128;
    ra.s[2] = Wr0; ra.d[2] = wr0h; ra.n[2] = 512 * 128;
    ra.s[3] = Wl1; ra.d[3] = wl1h; ra.n[3] = 512 * 512;
    ra.s[4] = Wr1; ra.d[4] = wr1h; ra.n[4] = 512 * 512;
    ra.s[5] = Wl2; ra.d[5] = wl2h; ra.n[5] = 256 * 512;
    ra.s[6] = Wr2; ra.d[6] = wr2h; ra.n[6] = 256 * 512;
    round_all_kernel<<<dim3(256, 7), 256, 0, s2>>>(ra);
    cudaEventRecord(eJoin, s2);

    // CSR build (main stream)
    zero_detect_kernel<<<(N_NODES + 255) / 256, 256>>>((const int*)ei);
    hist_kernel<<<(N_EDGES + 255) / 256, 256>>>(ei);
    scan1_kernel<<<50, 1024>>>();
    scan2_kernel<<<1, 64>>>();
    scan3_kernel<<<50, 1024>>>();
    scatter_kernel<<<(N_EDGES + 255) / 256, 256>>>(ei);

    // ---- join: everything below needs both CSR and fp16 buffers ----
    cudaStreamWaitEvent(0, eJoin, 0);

    int aggBlocks = (N_NODES * 32 + 255) / 256;
    int mTiles = (M + 127) / 128;

    // Layer 0: 128 -> 512, relu
    aggregate_kernel<128><<<aggBlocks, 256>>>(xh, aggh);
    gemm_h_kernel<true, true, false><<<dim3(mTiles, 4), 256, GEMM_SMEM>>>(
        aggh, wl0h, xh, wr0h, bl0, h1h, nullptr, M, 512, 128, 0);

    // Layer 1: 512 -> 512, relu
    aggregate_kernel<512><<<aggBlocks, 256>>>(h1h, aggh);
    gemm_h_kernel<true, true, false><<<dim3(mTiles, 4), 256, GEMM_SMEM>>>(
        aggh, wl1h, h1h, wr1h, bl1, h2h, nullptr, M, 512, 512, 0);

    // Layer 2 (projection-first, single GEMM over [Wl2;Wr2]):
    //   cols 0-255 -> Pl fp16, cols 256-511 -> Pr fp32
    gemm_h_kernel<false, false, true><<<dim3(mTiles, 4), 256, GEMM_SMEM>>>(
        h2h, wl2h, nullptr, nullptr, nullptr, Pl, Pr, M, 512, 512, 256);
    final_agg_kernel<<<aggBlocks, 256>>>(Pl, Pr, bl2, out);
}